// round 1
// baseline (speedup 1.0000x reference)
#include <cuda_runtime.h>
#include <cuda_bf16.h>
#include <math.h>

// ---------------- problem constants ----------------
#define BB   128           // batch
#define TT   256           // seq len
#define EE   256           // embed dim
#define H2   256           // hidden per dir
#define G4H  1024          // 4*H2
#define NT   76            // tags
#define START_IDX 74
#define STOP_IDX  75
#define NEGV (-10000.0f)

// ---------------- scratch (device globals; no allocs allowed) ----------------
// xw[d][b][t][k*4+g] : precomputed x@Wih^T + bias, gate-interleaved
__device__ float g_xw[(size_t)2 * BB * TT * G4H];          // 268 MB
// lstm_out[b][t][dir*256 + k]
__device__ float g_lstm[(size_t)BB * TT * 512];            // 67 MB
// feats[b][t][j]
__device__ float g_feats[(size_t)BB * TT * NT];            // 10 MB
// W2[d][kk][k][g] = Whh_d[g*256+k][kk]  (transposed, gate-interleaved)
__device__ float g_W2[(size_t)2 * 256 * 256 * 4];          // 2 MB

// ---------------- helpers ----------------
__device__ __forceinline__ float sigm(float x) {
    return 1.0f / (1.0f + expf(-x));
}

// ---------------- kernel 0: transpose Whh -> g_W2 ----------------
__global__ void transpose_whh_kernel(const float* __restrict__ Whh_f,
                                     const float* __restrict__ Whh_b) {
    size_t idx = (size_t)blockIdx.x * blockDim.x + threadIdx.x;
    const size_t total = (size_t)2 * 1024 * 256;
    if (idx >= total) return;
    int kk  = (int)(idx & 255);        // source column (fastest -> coalesced read)
    size_t r = idx >> 8;
    int row = (int)(r & 1023);         // row = g*256 + k
    int d   = (int)(r >> 10);
    int g = row >> 8;
    int k = row & 255;
    const float* W = d ? Whh_b : Whh_f;
    g_W2[(((size_t)d * 256 + kk) * 256 + k) * 4 + g] = W[(size_t)row * 256 + kk];
}

// ---------------- kernel 1: pre-GEMM xw = embed(ids) @ Wih^T + (bih+bhh) ----------------
// M = B*T = 32768 (m = b*T+t), N = 1024, K = 256. Tiles 64x64x32, 256 threads, 4x4 micro.
__global__ void __launch_bounds__(256) pregemm_kernel(
    const int*   __restrict__ ids,
    const float* __restrict__ emb,
    const float* __restrict__ Wih_f, const float* __restrict__ Wih_b,
    const float* __restrict__ bih_f, const float* __restrict__ bhh_f,
    const float* __restrict__ bih_b, const float* __restrict__ bhh_b)
{
    const int d = blockIdx.z;
    const float* __restrict__ Wih = d ? Wih_b : Wih_f;
    const float* __restrict__ b1  = d ? bih_b : bih_f;
    const float* __restrict__ b2  = d ? bhh_b : bhh_f;

    const int m0 = blockIdx.y * 64;
    const int n0 = blockIdx.x * 64;
    const int tid = threadIdx.x;

    __shared__ __align__(16) float As[32][68];   // [kk][m], padded
    __shared__ __align__(16) float Bs[32][68];   // [kk][n], padded
    __shared__ int ids_s[64];

    if (tid < 64) ids_s[tid] = ids[m0 + tid];
    __syncthreads();

    float acc[4][4];
#pragma unroll
    for (int i = 0; i < 4; i++)
#pragma unroll
        for (int j = 0; j < 4; j++) acc[i][j] = 0.0f;

    const int tm = (tid >> 4) * 4;
    const int tn = (tid & 15) * 4;

    for (int k0 = 0; k0 < 256; k0 += 32) {
#pragma unroll
        for (int it = 0; it < 2; it++) {
            int idx = tid + it * 256;      // 0..511 float4 slot
            int r   = idx >> 3;            // tile row 0..63
            int c4  = (idx & 7) * 4;       // col within 32
            float4 va = *(const float4*)(emb + (size_t)ids_s[r] * 256 + k0 + c4);
            As[c4 + 0][r] = va.x; As[c4 + 1][r] = va.y;
            As[c4 + 2][r] = va.z; As[c4 + 3][r] = va.w;
            float4 vb = *(const float4*)(Wih + (size_t)(n0 + r) * 256 + k0 + c4);
            Bs[c4 + 0][r] = vb.x; Bs[c4 + 1][r] = vb.y;
            Bs[c4 + 2][r] = vb.z; Bs[c4 + 3][r] = vb.w;
        }
        __syncthreads();
#pragma unroll
        for (int kk = 0; kk < 32; kk++) {
            float4 a = *(const float4*)&As[kk][tm];
            float4 b = *(const float4*)&Bs[kk][tn];
            float av[4] = {a.x, a.y, a.z, a.w};
            float bv[4] = {b.x, b.y, b.z, b.w};
#pragma unroll
            for (int i = 0; i < 4; i++)
#pragma unroll
                for (int j = 0; j < 4; j++)
                    acc[i][j] = fmaf(av[i], bv[j], acc[i][j]);
        }
        __syncthreads();
    }

#pragma unroll
    for (int i = 0; i < 4; i++) {
#pragma unroll
        for (int j = 0; j < 4; j++) {
            int m = m0 + tm + i;
            int n = n0 + tn + j;
            int g  = n >> 8;
            int kq = n & 255;
            g_xw[((size_t)d * (BB * TT) + m) * G4H + kq * 4 + g] =
                acc[i][j] + b1[n] + b2[n];
        }
    }
}

// ---------------- kernel 2: recurrent LSTM (both directions) ----------------
// 64 CTAs: bx>>5 = dir, bx&31 = batch group of 4. 256 threads: thread = hidden k.
// Per step: acc[bi] (float4 = gates i,f,g,o) init from xw, += Whh(h) via
// coalesced LDG of W2 and broadcast LDS of h. One barrier/step (double-buffered h).
__global__ void __launch_bounds__(256, 1) lstm_rec_kernel(
    const float* __restrict__ h0, const float* __restrict__ c0)
{
    const int bx  = blockIdx.x;
    const int d   = bx >> 5;
    const int grp = bx & 31;
    const int k   = threadIdx.x;
    const int b0  = grp * 4;

    __shared__ __align__(16) float h_s[2][4][256];

    const float* __restrict__ W2 = g_W2 + (size_t)d * (256 * 256 * 4);
    float c_reg[4];

#pragma unroll
    for (int bi = 0; bi < 4; bi++) {
        h_s[0][bi][k] = h0[((size_t)d * BB + b0 + bi) * H2 + k];
        c_reg[bi]     = c0[((size_t)d * BB + b0 + bi) * H2 + k];
    }
    __syncthreads();

    int cur = 0;
    const float* wp = W2 + k * 4;

    for (int step = 0; step < TT; step++) {
        const int t = d ? (TT - 1 - step) : step;

        float4 acc[4];
#pragma unroll
        for (int bi = 0; bi < 4; bi++)
            acc[bi] = *(const float4*)(g_xw +
                (((size_t)d * BB + b0 + bi) * TT + t) * G4H + k * 4);

        const float* hp = &h_s[cur][0][0];

#pragma unroll 2
        for (int kk = 0; kk < 256; kk += 4) {
            float4 w0 = *(const float4*)(wp + (size_t)(kk + 0) * 1024);
            float4 w1 = *(const float4*)(wp + (size_t)(kk + 1) * 1024);
            float4 w2 = *(const float4*)(wp + (size_t)(kk + 2) * 1024);
            float4 w3 = *(const float4*)(wp + (size_t)(kk + 3) * 1024);
#pragma unroll
            for (int bi = 0; bi < 4; bi++) {
                float4 hv = *(const float4*)(hp + bi * 256 + kk);
                acc[bi].x = fmaf(w0.x, hv.x, acc[bi].x);
                acc[bi].x = fmaf(w1.x, hv.y, acc[bi].x);
                acc[bi].x = fmaf(w2.x, hv.z, acc[bi].x);
                acc[bi].x = fmaf(w3.x, hv.w, acc[bi].x);
                acc[bi].y = fmaf(w0.y, hv.x, acc[bi].y);
                acc[bi].y = fmaf(w1.y, hv.y, acc[bi].y);
                acc[bi].y = fmaf(w2.y, hv.z, acc[bi].y);
                acc[bi].y = fmaf(w3.y, hv.w, acc[bi].y);
                acc[bi].z = fmaf(w0.z, hv.x, acc[bi].z);
                acc[bi].z = fmaf(w1.z, hv.y, acc[bi].z);
                acc[bi].z = fmaf(w2.z, hv.z, acc[bi].z);
                acc[bi].z = fmaf(w3.z, hv.w, acc[bi].z);
                acc[bi].w = fmaf(w0.w, hv.x, acc[bi].w);
                acc[bi].w = fmaf(w1.w, hv.y, acc[bi].w);
                acc[bi].w = fmaf(w2.w, hv.z, acc[bi].w);
                acc[bi].w = fmaf(w3.w, hv.w, acc[bi].w);
            }
        }

#pragma unroll
        for (int bi = 0; bi < 4; bi++) {
            float ig = sigm(acc[bi].x);
            float fg = sigm(acc[bi].y);
            float gg = tanhf(acc[bi].z);
            float og = sigm(acc[bi].w);
            float cn = fg * c_reg[bi] + ig * gg;
            c_reg[bi] = cn;
            float hn = og * tanhf(cn);
            h_s[cur ^ 1][bi][k] = hn;
            g_lstm[(((size_t)(b0 + bi)) * TT + t) * 512 + d * 256 + k] = hn;
        }
        __syncthreads();
        cur ^= 1;
    }
}

// ---------------- kernel 3: feats = lstm_out @ W_out^T + b_out ----------------
// 2048 CTAs x 256 threads; each CTA: 16 (b,t) rows x 76 tags, K=512 in 64-chunks.
__global__ void __launch_bounds__(256) feats_kernel(
    const float* __restrict__ W_out, const float* __restrict__ b_out)
{
    const int m0  = blockIdx.x * 16;
    const int tid = threadIdx.x;

    __shared__ __align__(16) float Ws[76][68];  // [j][kk], padded
    __shared__ __align__(16) float Xs[16][64];  // [r][kk]

    float acc[5] = {0.f, 0.f, 0.f, 0.f, 0.f};
    const int r  = tid >> 4;
    const int jg = tid & 15;

    for (int k0 = 0; k0 < 512; k0 += 64) {
        for (int idx = tid; idx < 76 * 16; idx += 256) {
            int row = idx >> 4;
            int c4  = (idx & 15) * 4;
            float4 v = *(const float4*)(W_out + (size_t)row * 512 + k0 + c4);
            *(float4*)&Ws[row][c4] = v;
        }
        {
            int row = tid >> 4;
            int c4  = (tid & 15) * 4;
            *(float4*)&Xs[row][c4] =
                *(const float4*)(g_lstm + (size_t)(m0 + row) * 512 + k0 + c4);
        }
        __syncthreads();
#pragma unroll
        for (int kk = 0; kk < 64; kk += 4) {
            float4 x = *(const float4*)&Xs[r][kk];
#pragma unroll
            for (int u = 0; u < 5; u++) {
                int j = jg + u * 16;
                if (j < NT) {
                    float4 w = *(const float4*)&Ws[j][kk];
                    acc[u] = fmaf(x.x, w.x, acc[u]);
                    acc[u] = fmaf(x.y, w.y, acc[u]);
                    acc[u] = fmaf(x.z, w.z, acc[u]);
                    acc[u] = fmaf(x.w, w.w, acc[u]);
                }
            }
        }
        __syncthreads();
    }

#pragma unroll
    for (int u = 0; u < 5; u++) {
        int j = jg + u * 16;
        if (j < NT)
            g_feats[(size_t)(m0 + r) * NT + j] = acc[u] + b_out[j];
    }
}

// ---------------- kernel 4: Viterbi (1 CTA per batch element) ----------------
__global__ void __launch_bounds__(128) viterbi_kernel(
    const float* __restrict__ trans, float* __restrict__ out)
{
    const int b   = blockIdx.x;
    const int tid = threadIdx.x;

    __shared__ float trans_s[NT * NT];
    __shared__ float fv0[NT], fv1[NT];
    __shared__ unsigned char bp[TT][NT];

    for (int i = tid; i < NT * NT; i += blockDim.x) trans_s[i] = trans[i];
    if (tid < NT) fv0[tid] = (tid == START_IDX) ? 0.0f : NEGV;
    __syncthreads();

    const float* __restrict__ feats_b = g_feats + (size_t)b * TT * NT;

    for (int t = 0; t < TT; t++) {
        float* fv  = (t & 1) ? fv1 : fv0;
        float* fvn = (t & 1) ? fv0 : fv1;
        if (tid < NT) {
            float best = -INFINITY;
            int arg = 0;
            const float* tr = trans_s + tid * NT;
#pragma unroll 4
            for (int p = 0; p < NT; p++) {
                float s = fv[p] + tr[p];   // fv[prev] + trans[next][prev]
                if (s > best) { best = s; arg = p; }   // first-max like jnp.argmax
            }
            fvn[tid] = best + feats_b[t * NT + tid];
            bp[t][tid] = (unsigned char)arg;
        }
        __syncthreads();
    }

    if (tid == 0) {
        // after t = 255 (odd), the latest fv lives in fv0
        float* fvF = fv0;
        float best = -INFINITY;
        int arg = 0;
        for (int j = 0; j < NT; j++) {
            float s = fvF[j] + trans_s[STOP_IDX * NT + j];
            if (s > best) { best = s; arg = j; }
        }
        out[b] = best;                         // score
        float* po = out + BB + (size_t)b * TT; // path (as float)
        int tag = arg;
        po[TT - 1] = (float)tag;
        for (int t = TT - 1; t >= 1; t--) {
            tag = bp[t][tag];
            po[t - 1] = (float)tag;
        }
    }
}

// ---------------- launch ----------------
extern "C" void kernel_launch(void* const* d_in, const int* in_sizes, int n_in,
                              void* d_out, int out_size) {
    const int*   ids    = (const int*)  d_in[0];
    const float* emb    = (const float*)d_in[1];
    const float* Wih_f  = (const float*)d_in[2];
    const float* Whh_f  = (const float*)d_in[3];
    const float* bih_f  = (const float*)d_in[4];
    const float* bhh_f  = (const float*)d_in[5];
    const float* Wih_b  = (const float*)d_in[6];
    const float* Whh_b  = (const float*)d_in[7];
    const float* bih_b  = (const float*)d_in[8];
    const float* bhh_b  = (const float*)d_in[9];
    const float* h0     = (const float*)d_in[10];
    const float* c0     = (const float*)d_in[11];
    const float* W_out  = (const float*)d_in[12];
    const float* b_out  = (const float*)d_in[13];
    const float* trans  = (const float*)d_in[14];
    float* out = (float*)d_out;

    (void)in_sizes; (void)n_in; (void)out_size;

    // 0) transpose Whh into gate-interleaved column-major layout
    {
        const size_t total = (size_t)2 * 1024 * 256;
        transpose_whh_kernel<<<(unsigned)((total + 255) / 256), 256>>>(Whh_f, Whh_b);
    }
    // 1) xw = embed(ids) @ Wih^T + bias  (both dirs)
    {
        dim3 grid(G4H / 64, (BB * TT) / 64, 2);
        pregemm_kernel<<<grid, 256>>>(ids, emb, Wih_f, Wih_b,
                                      bih_f, bhh_f, bih_b, bhh_b);
    }
    // 2) recurrent LSTM both directions
    lstm_rec_kernel<<<64, 256>>>(h0, c0);
    // 3) feats
    feats_kernel<<<(BB * TT) / 16, 256>>>(W_out, b_out);
    // 4) viterbi + output
    viterbi_kernel<<<BB, 128>>>(trans, out);
}

// round 2
// speedup vs baseline: 1.0872x; 1.0872x over previous
#include <cuda_runtime.h>
#include <cuda_bf16.h>
#include <math.h>

// ---------------- problem constants ----------------
#define BB   128
#define TT   256
#define EE   256
#define H2   256
#define G4H  1024
#define NT   76
#define START_IDX 74
#define STOP_IDX  75
#define NEGV (-10000.0f)

// ---------------- scratch ----------------
// xw[d][m][n], n = g*256+k (plain row-major)
__device__ __align__(16) float g_xw[(size_t)2 * BB * TT * G4H];
// lstm_out[b][t][dir*256 + k]
__device__ __align__(16) float g_lstm[(size_t)BB * TT * 512];
// feats[b][t][j]
__device__ __align__(16) float g_feats[(size_t)BB * TT * NT];
// W2[d][kk][k][g] = Whh_d[g*256+k][kk]
__device__ __align__(16) float g_W2[(size_t)2 * 256 * 256 * 4];

// ---------------- f32x2 helpers ----------------
typedef unsigned long long u64;

__device__ __forceinline__ u64 pk2(float lo, float hi) {
    u64 r; asm("mov.b64 %0, {%1, %2};" : "=l"(r) : "f"(lo), "f"(hi)); return r;
}
__device__ __forceinline__ void fma2(u64& d, u64 a, u64 b) {
    asm("fma.rn.f32x2 %0, %1, %2, %0;" : "+l"(d) : "l"(a), "l"(b));
}
__device__ __forceinline__ float2 upk2(u64 v) {
    float2 r; asm("mov.b64 {%0, %1}, %2;" : "=f"(r.x), "=f"(r.y) : "l"(v)); return r;
}
__device__ __forceinline__ float sigm(float x) {
    return 1.0f / (1.0f + expf(-x));
}

// ---------------- kernel 0: transpose Whh -> g_W2 ----------------
__global__ void transpose_whh_kernel(const float* __restrict__ Whh_f,
                                     const float* __restrict__ Whh_b) {
    size_t idx = (size_t)blockIdx.x * blockDim.x + threadIdx.x;
    const size_t total = (size_t)2 * 1024 * 256;
    if (idx >= total) return;
    int kk  = (int)(idx & 255);
    size_t r = idx >> 8;
    int row = (int)(r & 1023);
    int d   = (int)(r >> 10);
    int g = row >> 8;
    int k = row & 255;
    const float* W = d ? Whh_b : Whh_f;
    g_W2[(((size_t)d * 256 + kk) * 256 + k) * 4 + g] = W[(size_t)row * 256 + kk];
}

// ---------------- kernel 1: pre-GEMM (f32x2, 128x128 tile, 8x8 micro) ----------------
// M = 32768 (m=b*T+t), N = 1024, K = 256. KC=8 chunks, double-buffered smem.
#define KC 8
#define APAD 132
__global__ void __launch_bounds__(256, 2) pregemm_kernel(
    const int*   __restrict__ ids,
    const float* __restrict__ emb,
    const float* __restrict__ Wih_f, const float* __restrict__ Wih_b,
    const float* __restrict__ bih_f, const float* __restrict__ bhh_f,
    const float* __restrict__ bih_b, const float* __restrict__ bhh_b)
{
    const int d = blockIdx.z;
    const float* __restrict__ Wih = d ? Wih_b : Wih_f;
    const float* __restrict__ b1  = d ? bih_b : bih_f;
    const float* __restrict__ b2  = d ? bhh_b : bhh_f;

    const int m0 = blockIdx.y * 128;
    const int n0 = blockIdx.x * 128;
    const int tid = threadIdx.x;
    const int tx = tid & 15;        // n micro (8 cols)
    const int ty = tid >> 4;        // m micro (8 rows)

    __shared__ __align__(16) float As[2][KC][APAD];
    __shared__ __align__(16) float Bs[2][KC][APAD];
    __shared__ int ids_s[128];

    if (tid < 128) ids_s[tid] = ids[m0 + tid];
    __syncthreads();

    // per-thread gmem staging: 1 float4 of A and B per chunk
    const int lrow = tid >> 1;           // 0..127
    const int lc4  = (tid & 1) * 4;      // 0 or 4
    const float* ap = emb + (size_t)ids_s[lrow] * 256 + lc4;
    const float* bp = Wih + (size_t)(n0 + lrow) * 256 + lc4;

    // bias for this thread's 8 columns
    float bsum[8];
#pragma unroll
    for (int j = 0; j < 8; j++) {
        int n = n0 + tx * 8 + j;
        bsum[j] = b1[n] + b2[n];
    }

    u64 acc[8][4];
#pragma unroll
    for (int i = 0; i < 8; i++)
#pragma unroll
        for (int jp = 0; jp < 4; jp++) acc[i][jp] = 0ULL;

    float4 ra = *(const float4*)ap;
    float4 rb = *(const float4*)bp;

    const int NCH = 256 / KC;   // 32
    for (int ch = 0; ch < NCH; ch++) {
        const int wb = ch & 1;
        // stage chunk ch into smem
        As[wb][lc4 + 0][lrow] = ra.x; As[wb][lc4 + 1][lrow] = ra.y;
        As[wb][lc4 + 2][lrow] = ra.z; As[wb][lc4 + 3][lrow] = ra.w;
        Bs[wb][lc4 + 0][lrow] = rb.x; Bs[wb][lc4 + 1][lrow] = rb.y;
        Bs[wb][lc4 + 2][lrow] = rb.z; Bs[wb][lc4 + 3][lrow] = rb.w;
        // prefetch chunk ch+1
        if (ch + 1 < NCH) {
            ra = *(const float4*)(ap + (ch + 1) * KC);
            rb = *(const float4*)(bp + (ch + 1) * KC);
        }
        // compute chunk ch-1
        if (ch > 0) {
            const int rbuf = (ch - 1) & 1;
#pragma unroll
            for (int kk = 0; kk < KC; kk++) {
                float4 alo = *(const float4*)&As[rbuf][kk][ty * 8];
                float4 ahi = *(const float4*)&As[rbuf][kk][ty * 8 + 4];
                ulonglong2 blo = *(const ulonglong2*)&Bs[rbuf][kk][tx * 8];
                ulonglong2 bhi = *(const ulonglong2*)&Bs[rbuf][kk][tx * 8 + 4];
                float av[8] = {alo.x, alo.y, alo.z, alo.w, ahi.x, ahi.y, ahi.z, ahi.w};
#pragma unroll
                for (int i = 0; i < 8; i++) {
                    u64 a2 = pk2(av[i], av[i]);
                    fma2(acc[i][0], a2, blo.x);
                    fma2(acc[i][1], a2, blo.y);
                    fma2(acc[i][2], a2, bhi.x);
                    fma2(acc[i][3], a2, bhi.y);
                }
            }
        }
        __syncthreads();
    }
    // final chunk (NCH-1)
    {
        const int rbuf = (NCH - 1) & 1;
#pragma unroll
        for (int kk = 0; kk < KC; kk++) {
            float4 alo = *(const float4*)&As[rbuf][kk][ty * 8];
            float4 ahi = *(const float4*)&As[rbuf][kk][ty * 8 + 4];
            ulonglong2 blo = *(const ulonglong2*)&Bs[rbuf][kk][tx * 8];
            ulonglong2 bhi = *(const ulonglong2*)&Bs[rbuf][kk][tx * 8 + 4];
            float av[8] = {alo.x, alo.y, alo.z, alo.w, ahi.x, ahi.y, ahi.z, ahi.w};
#pragma unroll
            for (int i = 0; i < 8; i++) {
                u64 a2 = pk2(av[i], av[i]);
                fma2(acc[i][0], a2, blo.x);
                fma2(acc[i][1], a2, blo.y);
                fma2(acc[i][2], a2, bhi.x);
                fma2(acc[i][3], a2, bhi.y);
            }
        }
    }

    // epilogue: bias + coalesced store to g_xw[d][m][n]
#pragma unroll
    for (int i = 0; i < 8; i++) {
        int m = m0 + ty * 8 + i;
        float c[8];
#pragma unroll
        for (int jp = 0; jp < 4; jp++) {
            float2 v = upk2(acc[i][jp]);
            c[2 * jp] = v.x; c[2 * jp + 1] = v.y;
        }
        float* op = g_xw + ((size_t)d * (BB * TT) + m) * G4H + n0 + tx * 8;
        float4 v0 = {c[0] + bsum[0], c[1] + bsum[1], c[2] + bsum[2], c[3] + bsum[3]};
        float4 v1 = {c[4] + bsum[4], c[5] + bsum[5], c[6] + bsum[6], c[7] + bsum[7]};
        *(float4*)op = v0;
        *(float4*)(op + 4) = v1;
    }
}

// ---------------- kernel 2: recurrent LSTM (f32x2) ----------------
// 64 CTAs: (dir, 4-batch group). thread = hidden k. Gates as (i,f)|(g,o) u64 pairs.
// h stored smem-duplicated float2(h,h) so broadcast operand is pre-packed.
__global__ void __launch_bounds__(256, 1) lstm_rec_kernel(
    const float* __restrict__ h0, const float* __restrict__ c0)
{
    const int bx  = blockIdx.x;
    const int d   = bx >> 5;
    const int grp = bx & 31;
    const int k   = threadIdx.x;
    const int b0  = grp * 4;

    __shared__ __align__(16) float2 h2s[2][4][256];   // (h,h) duplicated

    const float* __restrict__ W2 = g_W2 + (size_t)d * (256 * 256 * 4);
    float c_reg[4];

#pragma unroll
    for (int bi = 0; bi < 4; bi++) {
        float hv = h0[((size_t)d * BB + b0 + bi) * H2 + k];
        h2s[0][bi][k] = make_float2(hv, hv);
        c_reg[bi] = c0[((size_t)d * BB + b0 + bi) * H2 + k];
    }
    __syncthreads();

    int cur = 0;
    const float* wp = W2 + k * 4;

    for (int step = 0; step < TT; step++) {
        const int t = d ? (TT - 1 - step) : step;

        u64 acc_if[4], acc_go[4];
#pragma unroll
        for (int bi = 0; bi < 4; bi++) {
            const float* xp = g_xw + (((size_t)d * BB + b0 + bi) * TT + t) * G4H;
            float xi = xp[k];
            float xf = xp[256 + k];
            float xg = xp[512 + k];
            float xo = xp[768 + k];
            acc_if[bi] = pk2(xi, xf);
            acc_go[bi] = pk2(xg, xo);
        }

        const float2* hp = &h2s[cur][0][0];

#pragma unroll 8
        for (int kk = 0; kk < 256; kk++) {
            ulonglong2 w = *(const ulonglong2*)(wp + (size_t)kk * 1024);
#pragma unroll
            for (int bi = 0; bi < 4; bi++) {
                u64 hh = *(const u64*)(hp + bi * 256 + kk);
                fma2(acc_if[bi], w.x, hh);
                fma2(acc_go[bi], w.y, hh);
            }
        }

#pragma unroll
        for (int bi = 0; bi < 4; bi++) {
            float2 gif = upk2(acc_if[bi]);
            float2 ggo = upk2(acc_go[bi]);
            float ig = sigm(gif.x);
            float fg = sigm(gif.y);
            float gg = tanhf(ggo.x);
            float og = sigm(ggo.y);
            float cn = fg * c_reg[bi] + ig * gg;
            c_reg[bi] = cn;
            float hn = og * tanhf(cn);
            h2s[cur ^ 1][bi][k] = make_float2(hn, hn);
            g_lstm[(((size_t)(b0 + bi)) * TT + t) * 512 + d * 256 + k] = hn;
        }
        __syncthreads();
        cur ^= 1;
    }
}

// ---------------- kernel 3: feats = lstm_out @ W_out^T + b_out ----------------
__global__ void __launch_bounds__(256) feats_kernel(
    const float* __restrict__ W_out, const float* __restrict__ b_out)
{
    const int m0  = blockIdx.x * 16;
    const int tid = threadIdx.x;

    __shared__ __align__(16) float Ws[76][68];
    __shared__ __align__(16) float Xs[16][64];

    float acc[5] = {0.f, 0.f, 0.f, 0.f, 0.f};
    const int r  = tid >> 4;
    const int jg = tid & 15;

    for (int k0 = 0; k0 < 512; k0 += 64) {
        for (int idx = tid; idx < 76 * 16; idx += 256) {
            int row = idx >> 4;
            int c4  = (idx & 15) * 4;
            float4 v = *(const float4*)(W_out + (size_t)row * 512 + k0 + c4);
            *(float4*)&Ws[row][c4] = v;
        }
        {
            int row = tid >> 4;
            int c4  = (tid & 15) * 4;
            *(float4*)&Xs[row][c4] =
                *(const float4*)(g_lstm + (size_t)(m0 + row) * 512 + k0 + c4);
        }
        __syncthreads();
#pragma unroll
        for (int kk = 0; kk < 64; kk += 4) {
            float4 x = *(const float4*)&Xs[r][kk];
#pragma unroll
            for (int u = 0; u < 5; u++) {
                int j = jg + u * 16;
                if (j < NT) {
                    float4 w = *(const float4*)&Ws[j][kk];
                    acc[u] = fmaf(x.x, w.x, acc[u]);
                    acc[u] = fmaf(x.y, w.y, acc[u]);
                    acc[u] = fmaf(x.z, w.z, acc[u]);
                    acc[u] = fmaf(x.w, w.w, acc[u]);
                }
            }
        }
        __syncthreads();
    }

#pragma unroll
    for (int u = 0; u < 5; u++) {
        int j = jg + u * 16;
        if (j < NT)
            g_feats[(size_t)(m0 + r) * NT + j] = acc[u] + b_out[j];
    }
}

// ---------------- kernel 4: Viterbi ----------------
__global__ void __launch_bounds__(128) viterbi_kernel(
    const float* __restrict__ trans, float* __restrict__ out)
{
    const int b   = blockIdx.x;
    const int tid = threadIdx.x;

    __shared__ float trans_s[NT * NT];
    __shared__ float fv0[NT], fv1[NT];
    __shared__ unsigned char bp[TT][NT];

    for (int i = tid; i < NT * NT; i += blockDim.x) trans_s[i] = trans[i];
    if (tid < NT) fv0[tid] = (tid == START_IDX) ? 0.0f : NEGV;
    __syncthreads();

    const float* __restrict__ feats_b = g_feats + (size_t)b * TT * NT;

    for (int t = 0; t < TT; t++) {
        float* fv  = (t & 1) ? fv1 : fv0;
        float* fvn = (t & 1) ? fv0 : fv1;
        if (tid < NT) {
            float best = -INFINITY;
            int arg = 0;
            const float* tr = trans_s + tid * NT;
#pragma unroll 4
            for (int p = 0; p < NT; p++) {
                float s = fv[p] + tr[p];
                if (s > best) { best = s; arg = p; }
            }
            fvn[tid] = best + feats_b[t * NT + tid];
            bp[t][tid] = (unsigned char)arg;
        }
        __syncthreads();
    }

    if (tid == 0) {
        float* fvF = fv0;
        float best = -INFINITY;
        int arg = 0;
        for (int j = 0; j < NT; j++) {
            float s = fvF[j] + trans_s[STOP_IDX * NT + j];
            if (s > best) { best = s; arg = j; }
        }
        out[b] = best;
        float* po = out + BB + (size_t)b * TT;
        int tag = arg;
        po[TT - 1] = (float)tag;
        for (int t = TT - 1; t >= 1; t--) {
            tag = bp[t][tag];
            po[t - 1] = (float)tag;
        }
    }
}

// ---------------- launch ----------------
extern "C" void kernel_launch(void* const* d_in, const int* in_sizes, int n_in,
                              void* d_out, int out_size) {
    const int*   ids    = (const int*)  d_in[0];
    const float* emb    = (const float*)d_in[1];
    const float* Wih_f  = (const float*)d_in[2];
    const float* Whh_f  = (const float*)d_in[3];
    const float* bih_f  = (const float*)d_in[4];
    const float* bhh_f  = (const float*)d_in[5];
    const float* Wih_b  = (const float*)d_in[6];
    const float* Whh_b  = (const float*)d_in[7];
    const float* bih_b  = (const float*)d_in[8];
    const float* bhh_b  = (const float*)d_in[9];
    const float* h0     = (const float*)d_in[10];
    const float* c0     = (const float*)d_in[11];
    const float* W_out  = (const float*)d_in[12];
    const float* b_out  = (const float*)d_in[13];
    const float* trans  = (const float*)d_in[14];
    float* out = (float*)d_out;

    (void)in_sizes; (void)n_in; (void)out_size;

    {
        const size_t total = (size_t)2 * 1024 * 256;
        transpose_whh_kernel<<<(unsigned)((total + 255) / 256), 256>>>(Whh_f, Whh_b);
    }
    {
        dim3 grid(G4H / 128, (BB * TT) / 128, 2);
        pregemm_kernel<<<grid, 256>>>(ids, emb, Wih_f, Wih_b,
                                      bih_f, bhh_f, bih_b, bhh_b);
    }
    lstm_rec_kernel<<<64, 256>>>(h0, c0);
    feats_kernel<<<(BB * TT) / 16, 256>>>(W_out, b_out);
    viterbi_kernel<<<BB, 128>>>(trans, out);
}

// round 3
// speedup vs baseline: 1.0875x; 1.0003x over previous
#include <cuda_runtime.h>
#include <cuda_bf16.h>
#include <math.h>

// ---------------- problem constants ----------------
#define BB   128
#define TT   256
#define EE   256
#define H2   256
#define G4H  1024
#define NT   76
#define START_IDX 74
#define STOP_IDX  75
#define NEGV (-10000.0f)

// ---------------- scratch ----------------
__device__ __align__(16) float g_xw[(size_t)2 * BB * TT * G4H];   // xw[d][m][n]
__device__ __align__(16) float g_lstm[(size_t)BB * TT * 512];     // [b][t][dir*256+k]
__device__ __align__(16) float g_feats[(size_t)BB * TT * NT];
__device__ __align__(16) float g_W2[(size_t)2 * 256 * 256 * 4];   // [d][kk][k][g]

// ---------------- f32x2 helpers ----------------
typedef unsigned long long u64;

__device__ __forceinline__ u64 pk2(float lo, float hi) {
    u64 r; asm("mov.b64 %0, {%1, %2};" : "=l"(r) : "f"(lo), "f"(hi)); return r;
}
__device__ __forceinline__ void fma2(u64& d, u64 a, u64 b) {
    asm("fma.rn.f32x2 %0, %1, %2, %0;" : "+l"(d) : "l"(a), "l"(b));
}
__device__ __forceinline__ float2 upk2(u64 v) {
    float2 r; asm("mov.b64 {%0, %1}, %2;" : "=f"(r.x), "=f"(r.y) : "l"(v)); return r;
}
__device__ __forceinline__ float sigm(float x) {
    return 1.0f / (1.0f + expf(-x));
}

// ---------------- kernel 0: transpose Whh -> g_W2 ----------------
__global__ void transpose_whh_kernel(const float* __restrict__ Whh_f,
                                     const float* __restrict__ Whh_b) {
    size_t idx = (size_t)blockIdx.x * blockDim.x + threadIdx.x;
    const size_t total = (size_t)2 * 1024 * 256;
    if (idx >= total) return;
    int kk  = (int)(idx & 255);
    size_t r = idx >> 8;
    int row = (int)(r & 1023);
    int d   = (int)(r >> 10);
    int g = row >> 8;
    int k = row & 255;
    const float* W = d ? Whh_b : Whh_f;
    g_W2[(((size_t)d * 256 + kk) * 256 + k) * 4 + g] = W[(size_t)row * 256 + kk];
}

// ---------------- kernel 1: pre-GEMM v3 ----------------
// CTA tile 128m x 64n, full K=256 staged in 192KB smem, ONE barrier, then a
// straight fma2 mainloop. Thread tile 8m x 4n (acc = 4 mpairs x 4 n, f32x2).
#define PGM 128
#define PGN 64
__global__ void __launch_bounds__(256, 1) pregemm_kernel(
    const int*   __restrict__ ids,
    const float* __restrict__ emb,
    const float* __restrict__ Wih_f, const float* __restrict__ Wih_b,
    const float* __restrict__ bih_f, const float* __restrict__ bhh_f,
    const float* __restrict__ bih_b, const float* __restrict__ bhh_b)
{
    extern __shared__ __align__(16) float sm[];
    float* As = sm;                  // [kk][m] 256*128
    float* Bs = sm + 256 * 128;      // [kk][n] 256*64
    __shared__ int ids_s[PGM];

    const int d = blockIdx.z;
    const float* __restrict__ Wih = d ? Wih_b : Wih_f;
    const float* __restrict__ b1  = d ? bih_b : bih_f;
    const float* __restrict__ b2  = d ? bhh_b : bhh_f;

    const int m0 = blockIdx.y * PGM;
    const int n0 = blockIdx.x * PGN;
    const int tid = threadIdx.x;

    if (tid < PGM) ids_s[tid] = ids[m0 + tid];
    __syncthreads();

    // stage A (embed gather, transposed to [kk][m])
    {
        const int r  = tid >> 1;
        const int ch = (tid & 1) * 128;
        const float* src = emb + (size_t)ids_s[r] * 256 + ch;
#pragma unroll
        for (int j = 0; j < 32; j++) {
            float4 v = *(const float4*)(src + j * 4);
            int c = ch + j * 4;
            As[(c + 0) * 128 + r] = v.x;
            As[(c + 1) * 128 + r] = v.y;
            As[(c + 2) * 128 + r] = v.z;
            As[(c + 3) * 128 + r] = v.w;
        }
    }
    // stage B (transposed to [kk][n])
    {
        const int r  = tid >> 2;
        const int ch = (tid & 3) * 64;
        const float* src = Wih + (size_t)(n0 + r) * 256 + ch;
#pragma unroll
        for (int j = 0; j < 16; j++) {
            float4 v = *(const float4*)(src + j * 4);
            int c = ch + j * 4;
            Bs[(c + 0) * 64 + r] = v.x;
            Bs[(c + 1) * 64 + r] = v.y;
            Bs[(c + 2) * 64 + r] = v.z;
            Bs[(c + 3) * 64 + r] = v.w;
        }
    }
    __syncthreads();

    const int tx = tid & 15;    // n group: 4 cols at tx*4
    const int ty = tid >> 4;    // m group: 8 rows at ty*8

    float bsum[4];
#pragma unroll
    for (int j = 0; j < 4; j++) {
        int n = n0 + tx * 4 + j;
        bsum[j] = b1[n] + b2[n];
    }

    u64 acc[4][4];   // [mpair][n]
#pragma unroll
    for (int p = 0; p < 4; p++)
#pragma unroll
        for (int j = 0; j < 4; j++) acc[p][j] = 0ULL;

    const float* ap = As + ty * 8;
    const float* bp = Bs + tx * 4;

#pragma unroll 4
    for (int kk = 0; kk < 256; kk++) {
        ulonglong2 a01 = *(const ulonglong2*)(ap + kk * 128);
        ulonglong2 a23 = *(const ulonglong2*)(ap + kk * 128 + 4);
        float4 b = *(const float4*)(bp + kk * 64);
        u64 bd[4];
        bd[0] = pk2(b.x, b.x); bd[1] = pk2(b.y, b.y);
        bd[2] = pk2(b.z, b.z); bd[3] = pk2(b.w, b.w);
#pragma unroll
        for (int j = 0; j < 4; j++) {
            fma2(acc[0][j], a01.x, bd[j]);
            fma2(acc[1][j], a01.y, bd[j]);
            fma2(acc[2][j], a23.x, bd[j]);
            fma2(acc[3][j], a23.y, bd[j]);
        }
    }

    // epilogue: coalesced float4 stores
#pragma unroll
    for (int p = 0; p < 4; p++) {
        float2 v0 = upk2(acc[p][0]);
        float2 v1 = upk2(acc[p][1]);
        float2 v2 = upk2(acc[p][2]);
        float2 v3 = upk2(acc[p][3]);
        int mA = m0 + ty * 8 + 2 * p;
        float4 rA = {v0.x + bsum[0], v1.x + bsum[1], v2.x + bsum[2], v3.x + bsum[3]};
        float4 rB = {v0.y + bsum[0], v1.y + bsum[1], v2.y + bsum[2], v3.y + bsum[3]};
        *(float4*)(g_xw + ((size_t)d * (BB * TT) + mA) * G4H + n0 + tx * 4) = rA;
        *(float4*)(g_xw + ((size_t)d * (BB * TT) + mA + 1) * G4H + n0 + tx * 4) = rB;
    }
}

// ---------------- kernel 2: recurrent LSTM (512 threads, kk-split) ----------------
// 64 CTAs: (dir, 4-batch group). tid = half*256 + k; each half reduces 128 kk,
// partials combined through smem. 16 warps/SM to hide L2 weight latency.
__global__ void __launch_bounds__(512, 1) lstm_rec_kernel(
    const float* __restrict__ h0, const float* __restrict__ c0)
{
    const int bx  = blockIdx.x;
    const int d   = bx >> 5;
    const int grp = bx & 31;
    const int b0  = grp * 4;
    const int tid = threadIdx.x;
    const int k    = tid & 255;
    const int half = tid >> 8;

    __shared__ __align__(16) float2 h2s[2][4][256];    // (h,h) duplicated
    __shared__ __align__(16) u64 psum[4][256][2];      // [bi][k][ifpair/gopair]

    const float* __restrict__ W2 = g_W2 + (size_t)d * (256 * 256 * 4);
    float c_reg[4];

    if (half == 0) {
#pragma unroll
        for (int bi = 0; bi < 4; bi++) {
            float hv = h0[((size_t)d * BB + b0 + bi) * H2 + k];
            h2s[0][bi][k] = make_float2(hv, hv);
            c_reg[bi] = c0[((size_t)d * BB + b0 + bi) * H2 + k];
        }
    }
    __syncthreads();

    int cur = 0;
    const float* wp = W2 + k * 4;
    const int kk0 = half * 128;

    for (int step = 0; step < TT; step++) {
        const int t = d ? (TT - 1 - step) : step;

        u64 aif[4], ago[4];
        if (half == 0) {
#pragma unroll
            for (int bi = 0; bi < 4; bi++) {
                const float* xp = g_xw + (((size_t)d * BB + b0 + bi) * TT + t) * G4H;
                aif[bi] = pk2(xp[k], xp[256 + k]);
                ago[bi] = pk2(xp[512 + k], xp[768 + k]);
            }
        } else {
#pragma unroll
            for (int bi = 0; bi < 4; bi++) { aif[bi] = 0ULL; ago[bi] = 0ULL; }
        }

        const float2* hp = &h2s[cur][0][0];

#pragma unroll 8
        for (int kk = kk0; kk < kk0 + 128; kk++) {
            ulonglong2 w = *(const ulonglong2*)(wp + (size_t)kk * 1024);
#pragma unroll
            for (int bi = 0; bi < 4; bi++) {
                u64 hh = *(const u64*)(hp + bi * 256 + kk);
                fma2(aif[bi], w.x, hh);
                fma2(ago[bi], w.y, hh);
            }
        }

        if (half == 1) {
#pragma unroll
            for (int bi = 0; bi < 4; bi++) {
                psum[bi][k][0] = aif[bi];
                psum[bi][k][1] = ago[bi];
            }
        }
        __syncthreads();

        if (half == 0) {
#pragma unroll
            for (int bi = 0; bi < 4; bi++) {
                float2 s_if = upk2(aif[bi]);
                float2 s_go = upk2(ago[bi]);
                float2 p_if = upk2(psum[bi][k][0]);
                float2 p_go = upk2(psum[bi][k][1]);
                float ig = sigm(s_if.x + p_if.x);
                float fg = sigm(s_if.y + p_if.y);
                float gg = tanhf(s_go.x + p_go.x);
                float og = sigm(s_go.y + p_go.y);
                float cn = fg * c_reg[bi] + ig * gg;
                c_reg[bi] = cn;
                float hn = og * tanhf(cn);
                h2s[cur ^ 1][bi][k] = make_float2(hn, hn);
                g_lstm[(((size_t)(b0 + bi)) * TT + t) * 512 + d * 256 + k] = hn;
            }
        }
        __syncthreads();
        cur ^= 1;
    }
}

// ---------------- kernel 3: feats = lstm_out @ W_out^T + b_out ----------------
__global__ void __launch_bounds__(256) feats_kernel(
    const float* __restrict__ W_out, const float* __restrict__ b_out)
{
    const int m0  = blockIdx.x * 16;
    const int tid = threadIdx.x;

    __shared__ __align__(16) float Ws[76][68];
    __shared__ __align__(16) float Xs[16][64];

    float acc[5] = {0.f, 0.f, 0.f, 0.f, 0.f};
    const int r  = tid >> 4;
    const int jg = tid & 15;

    for (int k0 = 0; k0 < 512; k0 += 64) {
        for (int idx = tid; idx < 76 * 16; idx += 256) {
            int row = idx >> 4;
            int c4  = (idx & 15) * 4;
            float4 v = *(const float4*)(W_out + (size_t)row * 512 + k0 + c4);
            *(float4*)&Ws[row][c4] = v;
        }
        {
            int row = tid >> 4;
            int c4  = (tid & 15) * 4;
            *(float4*)&Xs[row][c4] =
                *(const float4*)(g_lstm + (size_t)(m0 + row) * 512 + k0 + c4);
        }
        __syncthreads();
#pragma unroll
        for (int kk = 0; kk < 64; kk += 4) {
            float4 x = *(const float4*)&Xs[r][kk];
#pragma unroll
            for (int u = 0; u < 5; u++) {
                int j = jg + u * 16;
                if (j < NT) {
                    float4 w = *(const float4*)&Ws[j][kk];
                    acc[u] = fmaf(x.x, w.x, acc[u]);
                    acc[u] = fmaf(x.y, w.y, acc[u]);
                    acc[u] = fmaf(x.z, w.z, acc[u]);
                    acc[u] = fmaf(x.w, w.w, acc[u]);
                }
            }
        }
        __syncthreads();
    }

#pragma unroll
    for (int u = 0; u < 5; u++) {
        int j = jg + u * 16;
        if (j < NT)
            g_feats[(size_t)(m0 + r) * NT + j] = acc[u] + b_out[j];
    }
}

// ---------------- kernel 4: Viterbi ----------------
__global__ void __launch_bounds__(128) viterbi_kernel(
    const float* __restrict__ trans, float* __restrict__ out)
{
    const int b   = blockIdx.x;
    const int tid = threadIdx.x;

    __shared__ float trans_s[NT * NT];
    __shared__ float fv0[NT], fv1[NT];
    __shared__ unsigned char bp[TT][NT];

    for (int i = tid; i < NT * NT; i += blockDim.x) trans_s[i] = trans[i];
    if (tid < NT) fv0[tid] = (tid == START_IDX) ? 0.0f : NEGV;
    __syncthreads();

    const float* __restrict__ feats_b = g_feats + (size_t)b * TT * NT;

    for (int t = 0; t < TT; t++) {
        float* fv  = (t & 1) ? fv1 : fv0;
        float* fvn = (t & 1) ? fv0 : fv1;
        if (tid < NT) {
            float best = -INFINITY;
            int arg = 0;
            const float* tr = trans_s + tid * NT;
#pragma unroll 4
            for (int p = 0; p < NT; p++) {
                float s = fv[p] + tr[p];
                if (s > best) { best = s; arg = p; }
            }
            fvn[tid] = best + feats_b[t * NT + tid];
            bp[t][tid] = (unsigned char)arg;
        }
        __syncthreads();
    }

    if (tid == 0) {
        float* fvF = fv0;
        float best = -INFINITY;
        int arg = 0;
        for (int j = 0; j < NT; j++) {
            float s = fvF[j] + trans_s[STOP_IDX * NT + j];
            if (s > best) { best = s; arg = j; }
        }
        out[b] = best;
        float* po = out + BB + (size_t)b * TT;
        int tag = arg;
        po[TT - 1] = (float)tag;
        for (int t = TT - 1; t >= 1; t--) {
            tag = bp[t][tag];
            po[t - 1] = (float)tag;
        }
    }
}

// ---------------- launch ----------------
extern "C" void kernel_launch(void* const* d_in, const int* in_sizes, int n_in,
                              void* d_out, int out_size) {
    const int*   ids    = (const int*)  d_in[0];
    const float* emb    = (const float*)d_in[1];
    const float* Wih_f  = (const float*)d_in[2];
    const float* Whh_f  = (const float*)d_in[3];
    const float* bih_f  = (const float*)d_in[4];
    const float* bhh_f  = (const float*)d_in[5];
    const float* Wih_b  = (const float*)d_in[6];
    const float* Whh_b  = (const float*)d_in[7];
    const float* bih_b  = (const float*)d_in[8];
    const float* bhh_b  = (const float*)d_in[9];
    const float* h0     = (const float*)d_in[10];
    const float* c0     = (const float*)d_in[11];
    const float* W_out  = (const float*)d_in[12];
    const float* b_out  = (const float*)d_in[13];
    const float* trans  = (const float*)d_in[14];
    float* out = (float*)d_out;

    (void)in_sizes; (void)n_in; (void)out_size;

    {
        const size_t total = (size_t)2 * 1024 * 256;
        transpose_whh_kernel<<<(unsigned)((total + 255) / 256), 256>>>(Whh_f, Whh_b);
    }
    {
        const int smem_bytes = (256 * 128 + 256 * 64) * 4;   // 192 KB
        cudaFuncSetAttribute(pregemm_kernel,
                             cudaFuncAttributeMaxDynamicSharedMemorySize, smem_bytes);
        dim3 grid(G4H / PGN, (BB * TT) / PGM, 2);
        pregemm_kernel<<<grid, 256, smem_bytes>>>(ids, emb, Wih_f, Wih_b,
                                                  bih_f, bhh_f, bih_b, bhh_b);
    }
    lstm_rec_kernel<<<64, 512>>>(h0, c0);
    feats_kernel<<<(BB * TT) / 16, 256>>>(W_out, b_out);
    viterbi_kernel<<<BB, 128>>>(trans, out);
}

// round 4
// speedup vs baseline: 1.1369x; 1.0454x over previous
#include <cuda_runtime.h>
#include <cuda_bf16.h>
#include <math.h>

// ---------------- problem constants ----------------
#define BB   128
#define TT   256
#define EE   256
#define H2   256
#define G4H  1024
#define NT   76
#define START_IDX 74
#define STOP_IDX  75
#define NEGV (-10000.0f)

// ---------------- scratch ----------------
__device__ __align__(16) float g_xw[(size_t)2 * BB * TT * G4H];   // xw[d][m][n]
__device__ __align__(16) float g_lstm[(size_t)BB * TT * 512];     // [b][t][dir*256+k]
__device__ __align__(16) float g_feats[(size_t)BB * TT * NT];
// W3[d][ks][kk][kl][g] : kk-major slices per k-quarter
__device__ __align__(16) float g_W3[(size_t)2 * 4 * 256 * 64 * 4];

// ---------------- f32x2 helpers ----------------
typedef unsigned long long u64;

__device__ __forceinline__ u64 pk2(float lo, float hi) {
    u64 r; asm("mov.b64 %0, {%1, %2};" : "=l"(r) : "f"(lo), "f"(hi)); return r;
}
__device__ __forceinline__ void fma2(u64& d, u64 a, u64 b) {
    asm("fma.rn.f32x2 %0, %1, %2, %0;" : "+l"(d) : "l"(a), "l"(b));
}
__device__ __forceinline__ float2 upk2(u64 v) {
    float2 r; asm("mov.b64 {%0, %1}, %2;" : "=f"(r.x), "=f"(r.y) : "l"(v)); return r;
}
__device__ __forceinline__ float sigm(float x) {
    return 1.0f / (1.0f + expf(-x));
}
__device__ __forceinline__ unsigned smem_u32(const void* p) {
    unsigned a;
    asm("{ .reg .u64 t; cvta.to.shared.u64 t, %1; cvt.u32.u64 %0, t; }"
        : "=r"(a) : "l"(p));
    return a;
}
__device__ __forceinline__ void dsmem_st64(unsigned laddr, int rank, u64 v) {
    unsigned ra;
    asm volatile("mapa.shared::cluster.u32 %0, %1, %2;" : "=r"(ra) : "r"(laddr), "r"(rank));
    asm volatile("st.shared::cluster.b64 [%0], %1;" :: "r"(ra), "l"(v) : "memory");
}

// ---------------- kernel 0: transpose Whh -> g_W3 ----------------
__global__ void transpose_whh_kernel(const float* __restrict__ Whh_f,
                                     const float* __restrict__ Whh_b) {
    size_t idx = (size_t)blockIdx.x * blockDim.x + threadIdx.x;
    const size_t total = (size_t)2 * 1024 * 256;
    if (idx >= total) return;
    int kk  = (int)(idx & 255);
    size_t r = idx >> 8;
    int row = (int)(r & 1023);
    int d   = (int)(r >> 10);
    int g  = row >> 8;
    int k  = row & 255;
    int ks = k >> 6;
    int kl = k & 63;
    const float* W = d ? Whh_b : Whh_f;
    g_W3[((((size_t)(d * 4 + ks)) * 256 + kk) * 64 + kl) * 4 + g] =
        W[(size_t)row * 256 + kk];
}

// ---------------- kernel 1: pre-GEMM v3 (unchanged) ----------------
#define PGM 128
#define PGN 64
__global__ void __launch_bounds__(256, 1) pregemm_kernel(
    const int*   __restrict__ ids,
    const float* __restrict__ emb,
    const float* __restrict__ Wih_f, const float* __restrict__ Wih_b,
    const float* __restrict__ bih_f, const float* __restrict__ bhh_f,
    const float* __restrict__ bih_b, const float* __restrict__ bhh_b)
{
    extern __shared__ __align__(16) float sm[];
    float* As = sm;                  // [kk][m] 256*128
    float* Bs = sm + 256 * 128;      // [kk][n] 256*64
    __shared__ int ids_s[PGM];

    const int d = blockIdx.z;
    const float* __restrict__ Wih = d ? Wih_b : Wih_f;
    const float* __restrict__ b1  = d ? bih_b : bih_f;
    const float* __restrict__ b2  = d ? bhh_b : bhh_f;

    const int m0 = blockIdx.y * PGM;
    const int n0 = blockIdx.x * PGN;
    const int tid = threadIdx.x;

    if (tid < PGM) ids_s[tid] = ids[m0 + tid];
    __syncthreads();

    {
        const int r  = tid >> 1;
        const int ch = (tid & 1) * 128;
        const float* src = emb + (size_t)ids_s[r] * 256 + ch;
#pragma unroll
        for (int j = 0; j < 32; j++) {
            float4 v = *(const float4*)(src + j * 4);
            int c = ch + j * 4;
            As[(c + 0) * 128 + r] = v.x;
            As[(c + 1) * 128 + r] = v.y;
            As[(c + 2) * 128 + r] = v.z;
            As[(c + 3) * 128 + r] = v.w;
        }
    }
    {
        const int r  = tid >> 2;
        const int ch = (tid & 3) * 64;
        const float* src = Wih + (size_t)(n0 + r) * 256 + ch;
#pragma unroll
        for (int j = 0; j < 16; j++) {
            float4 v = *(const float4*)(src + j * 4);
            int c = ch + j * 4;
            Bs[(c + 0) * 64 + r] = v.x;
            Bs[(c + 1) * 64 + r] = v.y;
            Bs[(c + 2) * 64 + r] = v.z;
            Bs[(c + 3) * 64 + r] = v.w;
        }
    }
    __syncthreads();

    const int tx = tid & 15;
    const int ty = tid >> 4;

    float bsum[4];
#pragma unroll
    for (int j = 0; j < 4; j++) {
        int n = n0 + tx * 4 + j;
        bsum[j] = b1[n] + b2[n];
    }

    u64 acc[4][4];
#pragma unroll
    for (int p = 0; p < 4; p++)
#pragma unroll
        for (int j = 0; j < 4; j++) acc[p][j] = 0ULL;

    const float* ap = As + ty * 8;
    const float* bp = Bs + tx * 4;

#pragma unroll 4
    for (int kk = 0; kk < 256; kk++) {
        ulonglong2 a01 = *(const ulonglong2*)(ap + kk * 128);
        ulonglong2 a23 = *(const ulonglong2*)(ap + kk * 128 + 4);
        float4 b = *(const float4*)(bp + kk * 64);
        u64 bd[4];
        bd[0] = pk2(b.x, b.x); bd[1] = pk2(b.y, b.y);
        bd[2] = pk2(b.z, b.z); bd[3] = pk2(b.w, b.w);
#pragma unroll
        for (int j = 0; j < 4; j++) {
            fma2(acc[0][j], a01.x, bd[j]);
            fma2(acc[1][j], a01.y, bd[j]);
            fma2(acc[2][j], a23.x, bd[j]);
            fma2(acc[3][j], a23.y, bd[j]);
        }
    }

#pragma unroll
    for (int p = 0; p < 4; p++) {
        float2 v0 = upk2(acc[p][0]);
        float2 v1 = upk2(acc[p][1]);
        float2 v2 = upk2(acc[p][2]);
        float2 v3 = upk2(acc[p][3]);
        int mA = m0 + ty * 8 + 2 * p;
        float4 rA = {v0.x + bsum[0], v1.x + bsum[1], v2.x + bsum[2], v3.x + bsum[3]};
        float4 rB = {v0.y + bsum[0], v1.y + bsum[1], v2.y + bsum[2], v3.y + bsum[3]};
        *(float4*)(g_xw + ((size_t)d * (BB * TT) + mA) * G4H + n0 + tx * 4) = rA;
        *(float4*)(g_xw + ((size_t)d * (BB * TT) + mA + 1) * G4H + n0 + tx * 4) = rB;
    }
}

// ---------------- kernel 2: recurrent LSTM (cluster-4 k-split, G=8) ----------------
// 128 CTAs = 2 dir x 16 groups(G=8 batches) x 4 k-slices (cluster).
// Thread t: kl = t>>2 (0..63), bq = t&3; owns gates for k = rank*64+kl,
// batches bq and bq+4. Weights streamed from L2 (1 line/warp/kk).
// h exchanged across the cluster via DSMEM each step + 1 cluster barrier.
#define HPAD 258
__global__ void __cluster_dims__(4, 1, 1) __launch_bounds__(256, 1)
lstm_rec_kernel(const float* __restrict__ h0, const float* __restrict__ c0)
{
    const int cid  = blockIdx.x >> 2;
    const int rank = blockIdx.x & 3;
    const int d    = cid >> 4;
    const int grp  = cid & 15;
    const int b0   = grp * 8;
    const int tid  = threadIdx.x;
    const int kl   = tid >> 2;
    const int bq   = tid & 3;
    const int kg   = rank * 64 + kl;

    __shared__ __align__(16) float2 h2[2][8][HPAD];   // (h,h) dup, padded rows

    // init: every CTA loads the FULL h(0) for its 8 batches (local only)
#pragma unroll
    for (int bi = 0; bi < 8; bi++) {
        float hv = h0[((size_t)d * BB + b0 + bi) * H2 + tid];
        h2[0][bi][tid] = make_float2(hv, hv);
    }
    float c_reg[2];
#pragma unroll
    for (int j = 0; j < 2; j++)
        c_reg[j] = c0[((size_t)d * BB + b0 + bq + 4 * j) * H2 + kg];
    __syncthreads();

    const float* __restrict__ wbase =
        g_W3 + ((size_t)(d * 4 + rank)) * (256 * 64 * 4) + kl * 4;

    for (int step = 0; step < TT; step++) {
        const int t   = d ? (TT - 1 - step) : step;
        const int cur = step & 1;
        const int nxt = cur ^ 1;

        u64 aif[2], ago[2];
#pragma unroll
        for (int j = 0; j < 2; j++) {
            const float* xp =
                g_xw + (((size_t)d * BB + b0 + bq + 4 * j) * TT + t) * G4H;
            aif[j] = pk2(xp[kg], xp[256 + kg]);
            ago[j] = pk2(xp[512 + kg], xp[768 + kg]);
        }

        const float2* hp0 = &h2[cur][bq][0];
        const float2* hp1 = &h2[cur][bq + 4][0];

#pragma unroll 8
        for (int kk = 0; kk < 256; kk++) {
            ulonglong2 w = *(const ulonglong2*)(wbase + (size_t)kk * 256);
            u64 ha = *(const u64*)(hp0 + kk);
            u64 hb = *(const u64*)(hp1 + kk);
            fma2(aif[0], w.x, ha);
            fma2(ago[0], w.y, ha);
            fma2(aif[1], w.x, hb);
            fma2(ago[1], w.y, hb);
        }

#pragma unroll
        for (int j = 0; j < 2; j++) {
            const int bi = bq + 4 * j;
            float2 gif = upk2(aif[j]);
            float2 ggo = upk2(ago[j]);
            float ig = sigm(gif.x);
            float fg = sigm(gif.y);
            float gg = tanhf(ggo.x);
            float og = sigm(ggo.y);
            float cn = fg * c_reg[j] + ig * gg;
            c_reg[j] = cn;
            float hn = og * tanhf(cn);
            u64 hdup = pk2(hn, hn);
            unsigned laddr = smem_u32(&h2[nxt][bi][kg]);
#pragma unroll
            for (int r = 0; r < 4; r++) dsmem_st64(laddr, r, hdup);
            g_lstm[(((size_t)(b0 + bi)) * TT + t) * 512 + d * 256 + kg] = hn;
        }

        asm volatile("barrier.cluster.arrive.aligned;" ::: "memory");
        asm volatile("barrier.cluster.wait.aligned;" ::: "memory");
    }
}

// ---------------- kernel 3: feats = lstm_out @ W_out^T + b_out ----------------
__global__ void __launch_bounds__(256) feats_kernel(
    const float* __restrict__ W_out, const float* __restrict__ b_out)
{
    const int m0  = blockIdx.x * 16;
    const int tid = threadIdx.x;

    __shared__ __align__(16) float Ws[76][68];
    __shared__ __align__(16) float Xs[16][64];

    float acc[5] = {0.f, 0.f, 0.f, 0.f, 0.f};
    const int r  = tid >> 4;
    const int jg = tid & 15;

    for (int k0 = 0; k0 < 512; k0 += 64) {
        for (int idx = tid; idx < 76 * 16; idx += 256) {
            int row = idx >> 4;
            int c4  = (idx & 15) * 4;
            float4 v = *(const float4*)(W_out + (size_t)row * 512 + k0 + c4);
            *(float4*)&Ws[row][c4] = v;
        }
        {
            int row = tid >> 4;
            int c4  = (tid & 15) * 4;
            *(float4*)&Xs[row][c4] =
                *(const float4*)(g_lstm + (size_t)(m0 + row) * 512 + k0 + c4);
        }
        __syncthreads();
#pragma unroll
        for (int kk = 0; kk < 64; kk += 4) {
            float4 x = *(const float4*)&Xs[r][kk];
#pragma unroll
            for (int u = 0; u < 5; u++) {
                int j = jg + u * 16;
                if (j < NT) {
                    float4 w = *(const float4*)&Ws[j][kk];
                    acc[u] = fmaf(x.x, w.x, acc[u]);
                    acc[u] = fmaf(x.y, w.y, acc[u]);
                    acc[u] = fmaf(x.z, w.z, acc[u]);
                    acc[u] = fmaf(x.w, w.w, acc[u]);
                }
            }
        }
        __syncthreads();
    }

#pragma unroll
    for (int u = 0; u < 5; u++) {
        int j = jg + u * 16;
        if (j < NT)
            g_feats[(size_t)(m0 + r) * NT + j] = acc[u] + b_out[j];
    }
}

// ---------------- kernel 4: Viterbi ----------------
__global__ void __launch_bounds__(128) viterbi_kernel(
    const float* __restrict__ trans, float* __restrict__ out)
{
    const int b   = blockIdx.x;
    const int tid = threadIdx.x;

    __shared__ float trans_s[NT * NT];
    __shared__ float fv0[NT], fv1[NT];
    __shared__ unsigned char bp[TT][NT];

    for (int i = tid; i < NT * NT; i += blockDim.x) trans_s[i] = trans[i];
    if (tid < NT) fv0[tid] = (tid == START_IDX) ? 0.0f : NEGV;
    __syncthreads();

    const float* __restrict__ feats_b = g_feats + (size_t)b * TT * NT;

    for (int t = 0; t < TT; t++) {
        float* fv  = (t & 1) ? fv1 : fv0;
        float* fvn = (t & 1) ? fv0 : fv1;
        if (tid < NT) {
            float best = -INFINITY;
            int arg = 0;
            const float* tr = trans_s + tid * NT;
#pragma unroll 4
            for (int p = 0; p < NT; p++) {
                float s = fv[p] + tr[p];
                if (s > best) { best = s; arg = p; }
            }
            fvn[tid] = best + feats_b[t * NT + tid];
            bp[t][tid] = (unsigned char)arg;
        }
        __syncthreads();
    }

    if (tid == 0) {
        float* fvF = fv0;
        float best = -INFINITY;
        int arg = 0;
        for (int j = 0; j < NT; j++) {
            float s = fvF[j] + trans_s[STOP_IDX * NT + j];
            if (s > best) { best = s; arg = j; }
        }
        out[b] = best;
        float* po = out + BB + (size_t)b * TT;
        int tag = arg;
        po[TT - 1] = (float)tag;
        for (int t = TT - 1; t >= 1; t--) {
            tag = bp[t][tag];
            po[t - 1] = (float)tag;
        }
    }
}

// ---------------- launch ----------------
extern "C" void kernel_launch(void* const* d_in, const int* in_sizes, int n_in,
                              void* d_out, int out_size) {
    const int*   ids    = (const int*)  d_in[0];
    const float* emb    = (const float*)d_in[1];
    const float* Wih_f  = (const float*)d_in[2];
    const float* Whh_f  = (const float*)d_in[3];
    const float* bih_f  = (const float*)d_in[4];
    const float* bhh_f  = (const float*)d_in[5];
    const float* Wih_b  = (const float*)d_in[6];
    const float* Whh_b  = (const float*)d_in[7];
    const float* bih_b  = (const float*)d_in[8];
    const float* bhh_b  = (const float*)d_in[9];
    const float* h0     = (const float*)d_in[10];
    const float* c0     = (const float*)d_in[11];
    const float* W_out  = (const float*)d_in[12];
    const float* b_out  = (const float*)d_in[13];
    const float* trans  = (const float*)d_in[14];
    float* out = (float*)d_out;

    (void)in_sizes; (void)n_in; (void)out_size;

    {
        const size_t total = (size_t)2 * 1024 * 256;
        transpose_whh_kernel<<<(unsigned)((total + 255) / 256), 256>>>(Whh_f, Whh_b);
    }
    {
        const int smem_bytes = (256 * 128 + 256 * 64) * 4;   // 192 KB
        cudaFuncSetAttribute(pregemm_kernel,
                             cudaFuncAttributeMaxDynamicSharedMemorySize, smem_bytes);
        dim3 grid(G4H / PGN, (BB * TT) / PGM, 2);
        pregemm_kernel<<<grid, 256, smem_bytes>>>(ids, emb, Wih_f, Wih_b,
                                                  bih_f, bhh_f, bih_b, bhh_b);
    }
    lstm_rec_kernel<<<128, 256>>>(h0, c0);
    feats_kernel<<<(BB * TT) / 16, 256>>>(W_out, b_out);
    viterbi_kernel<<<BB, 128>>>(trans, out);
}

// round 5
// speedup vs baseline: 1.1533x; 1.0144x over previous
#include <cuda_runtime.h>
#include <cuda_bf16.h>
#include <math.h>

// ---------------- problem constants ----------------
#define BB   128
#define TT   256
#define EE   256
#define H2   256
#define G4H  1024
#define NT   76
#define START_IDX 74
#define STOP_IDX  75
#define NEGV (-10000.0f)

// ---------------- scratch ----------------
__device__ __align__(16) float g_xw[(size_t)2 * BB * TT * G4H];   // xw[d][m][n]
__device__ __align__(16) float g_lstm[(size_t)BB * TT * 512];     // [b][t][dir*256+k]
__device__ __align__(16) float g_feats[(size_t)BB * TT * NT];
// W3[d][ks][kk][kl][g] : kk-major slices per k-quarter
__device__ __align__(16) float g_W3[(size_t)2 * 4 * 256 * 64 * 4];

// ---------------- f32x2 helpers ----------------
typedef unsigned long long u64;

__device__ __forceinline__ u64 pk2(float lo, float hi) {
    u64 r; asm("mov.b64 %0, {%1, %2};" : "=l"(r) : "f"(lo), "f"(hi)); return r;
}
__device__ __forceinline__ void fma2(u64& d, u64 a, u64 b) {
    asm("fma.rn.f32x2 %0, %1, %2, %0;" : "+l"(d) : "l"(a), "l"(b));
}
__device__ __forceinline__ float2 upk2(u64 v) {
    float2 r; asm("mov.b64 {%0, %1}, %2;" : "=f"(r.x), "=f"(r.y) : "l"(v)); return r;
}
__device__ __forceinline__ float sigm(float x) {
    return 1.0f / (1.0f + expf(-x));
}
__device__ __forceinline__ unsigned smem_u32(const void* p) {
    unsigned a;
    asm("{ .reg .u64 t; cvta.to.shared.u64 t, %1; cvt.u32.u64 %0, t; }"
        : "=r"(a) : "l"(p));
    return a;
}
__device__ __forceinline__ void dsmem_st64(unsigned laddr, int rank, u64 v) {
    unsigned ra;
    asm volatile("mapa.shared::cluster.u32 %0, %1, %2;" : "=r"(ra) : "r"(laddr), "r"(rank));
    asm volatile("st.shared::cluster.b64 [%0], %1;" :: "r"(ra), "l"(v) : "memory");
}

// ---------------- kernel -1: no-op (shifts ncu capture slot onto lstm) ----------------
__global__ void noop_kernel() {}

// ---------------- kernel 0: transpose Whh -> g_W3 ----------------
__global__ void transpose_whh_kernel(const float* __restrict__ Whh_f,
                                     const float* __restrict__ Whh_b) {
    size_t idx = (size_t)blockIdx.x * blockDim.x + threadIdx.x;
    const size_t total = (size_t)2 * 1024 * 256;
    if (idx >= total) return;
    int kk  = (int)(idx & 255);
    size_t r = idx >> 8;
    int row = (int)(r & 1023);
    int d   = (int)(r >> 10);
    int g  = row >> 8;
    int k  = row & 255;
    int ks = k >> 6;
    int kl = k & 63;
    const float* W = d ? Whh_b : Whh_f;
    g_W3[((((size_t)(d * 4 + ks)) * 256 + kk) * 64 + kl) * 4 + g] =
        W[(size_t)row * 256 + kk];
}

// ---------------- kernel 1: pre-GEMM v4 ----------------
// CTA tile 128m x 64n, K staged in TWO 128-halves (96KB smem -> 2 CTAs/SM).
// Accumulation order kk = 0..255 ascending, identical to v3 (bitwise-same).
#define PGM 128
#define PGN 64
__global__ void __launch_bounds__(256, 2) pregemm_kernel(
    const int*   __restrict__ ids,
    const float* __restrict__ emb,
    const float* __restrict__ Wih_f, const float* __restrict__ Wih_b,
    const float* __restrict__ bih_f, const float* __restrict__ bhh_f,
    const float* __restrict__ bih_b, const float* __restrict__ bhh_b)
{
    extern __shared__ __align__(16) float sm[];
    float* As = sm;                  // [kk 0..127][m 0..127]
    float* Bs = sm + 128 * 128;      // [kk 0..127][n 0..63]
    __shared__ int ids_s[PGM];

    const int d = blockIdx.z;
    const float* __restrict__ Wih = d ? Wih_b : Wih_f;
    const float* __restrict__ b1  = d ? bih_b : bih_f;
    const float* __restrict__ b2  = d ? bhh_b : bhh_f;

    const int m0 = blockIdx.y * PGM;
    const int n0 = blockIdx.x * PGN;
    const int tid = threadIdx.x;

    if (tid < PGM) ids_s[tid] = ids[m0 + tid];
    __syncthreads();

    const int tx = tid & 15;    // n group: 4 cols at tx*4
    const int ty = tid >> 4;    // m group: 8 rows at ty*8

    float bsum[4];
#pragma unroll
    for (int j = 0; j < 4; j++) {
        int n = n0 + tx * 4 + j;
        bsum[j] = b1[n] + b2[n];
    }

    u64 acc[4][4];   // [mpair][n]
#pragma unroll
    for (int p = 0; p < 4; p++)
#pragma unroll
        for (int j = 0; j < 4; j++) acc[p][j] = 0ULL;

    const float* ap = As + ty * 8;
    const float* bp = Bs + tx * 4;

    // A-staging thread map: row = tid>>1, 64 cols at (tid&1)*64
    const int ar  = tid >> 1;
    const int ac0 = (tid & 1) * 64;
    const float* asrc = emb + (size_t)ids_s[ar] * 256 + ac0;
    // B-staging thread map: row = tid>>2, 32 cols at (tid&3)*32
    const int br  = tid >> 2;
    const int bc0 = (tid & 3) * 32;
    const float* bsrc = Wih + (size_t)(n0 + br) * 256 + bc0;

#pragma unroll
    for (int h = 0; h < 2; h++) {
        // stage A half (transposed to [kk][m])
        {
            const float* src = asrc + h * 128;
#pragma unroll
            for (int j = 0; j < 16; j++) {
                float4 v = *(const float4*)(src + j * 4);
                int c = ac0 + j * 4;
                As[(c + 0) * 128 + ar] = v.x;
                As[(c + 1) * 128 + ar] = v.y;
                As[(c + 2) * 128 + ar] = v.z;
                As[(c + 3) * 128 + ar] = v.w;
            }
        }
        // stage B half (transposed to [kk][n])
        {
            const float* src = bsrc + h * 128;
#pragma unroll
            for (int j = 0; j < 8; j++) {
                float4 v = *(const float4*)(src + j * 4);
                int c = bc0 + j * 4;
                Bs[(c + 0) * 64 + br] = v.x;
                Bs[(c + 1) * 64 + br] = v.y;
                Bs[(c + 2) * 64 + br] = v.z;
                Bs[(c + 3) * 64 + br] = v.w;
            }
        }
        __syncthreads();

#pragma unroll 4
        for (int kk = 0; kk < 128; kk++) {
            ulonglong2 a01 = *(const ulonglong2*)(ap + kk * 128);
            ulonglong2 a23 = *(const ulonglong2*)(ap + kk * 128 + 4);
            float4 b = *(const float4*)(bp + kk * 64);
            u64 bd[4];
            bd[0] = pk2(b.x, b.x); bd[1] = pk2(b.y, b.y);
            bd[2] = pk2(b.z, b.z); bd[3] = pk2(b.w, b.w);
#pragma unroll
            for (int j = 0; j < 4; j++) {
                fma2(acc[0][j], a01.x, bd[j]);
                fma2(acc[1][j], a01.y, bd[j]);
                fma2(acc[2][j], a23.x, bd[j]);
                fma2(acc[3][j], a23.y, bd[j]);
            }
        }
        __syncthreads();
    }

    // epilogue: coalesced float4 stores
#pragma unroll
    for (int p = 0; p < 4; p++) {
        float2 v0 = upk2(acc[p][0]);
        float2 v1 = upk2(acc[p][1]);
        float2 v2 = upk2(acc[p][2]);
        float2 v3 = upk2(acc[p][3]);
        int mA = m0 + ty * 8 + 2 * p;
        float4 rA = {v0.x + bsum[0], v1.x + bsum[1], v2.x + bsum[2], v3.x + bsum[3]};
        float4 rB = {v0.y + bsum[0], v1.y + bsum[1], v2.y + bsum[2], v3.y + bsum[3]};
        *(float4*)(g_xw + ((size_t)d * (BB * TT) + mA) * G4H + n0 + tx * 4) = rA;
        *(float4*)(g_xw + ((size_t)d * (BB * TT) + mA + 1) * G4H + n0 + tx * 4) = rB;
    }
}

// ---------------- kernel 2: recurrent LSTM (cluster-4 k-split, G=8) ----------------
#define HPAD 258
__global__ void __cluster_dims__(4, 1, 1) __launch_bounds__(256, 1)
lstm_rec_kernel(const float* __restrict__ h0, const float* __restrict__ c0)
{
    const int cid  = blockIdx.x >> 2;
    const int rank = blockIdx.x & 3;
    const int d    = cid >> 4;
    const int grp  = cid & 15;
    const int b0   = grp * 8;
    const int tid  = threadIdx.x;
    const int kl   = tid >> 2;
    const int bq   = tid & 3;
    const int kg   = rank * 64 + kl;

    __shared__ __align__(16) float2 h2[2][8][HPAD];   // (h,h) dup, padded rows

#pragma unroll
    for (int bi = 0; bi < 8; bi++) {
        float hv = h0[((size_t)d * BB + b0 + bi) * H2 + tid];
        h2[0][bi][tid] = make_float2(hv, hv);
    }
    float c_reg[2];
#pragma unroll
    for (int j = 0; j < 2; j++)
        c_reg[j] = c0[((size_t)d * BB + b0 + bq + 4 * j) * H2 + kg];
    __syncthreads();

    const float* __restrict__ wbase =
        g_W3 + ((size_t)(d * 4 + rank)) * (256 * 64 * 4) + kl * 4;

    for (int step = 0; step < TT; step++) {
        const int t   = d ? (TT - 1 - step) : step;
        const int cur = step & 1;
        const int nxt = cur ^ 1;

        u64 aif[2], ago[2];
#pragma unroll
        for (int j = 0; j < 2; j++) {
            const float* xp =
                g_xw + (((size_t)d * BB + b0 + bq + 4 * j) * TT + t) * G4H;
            aif[j] = pk2(xp[kg], xp[256 + kg]);
            ago[j] = pk2(xp[512 + kg], xp[768 + kg]);
        }

        const float2* hp0 = &h2[cur][bq][0];
        const float2* hp1 = &h2[cur][bq + 4][0];

#pragma unroll 8
        for (int kk = 0; kk < 256; kk++) {
            ulonglong2 w = *(const ulonglong2*)(wbase + (size_t)kk * 256);
            u64 ha = *(const u64*)(hp0 + kk);
            u64 hb = *(const u64*)(hp1 + kk);
            fma2(aif[0], w.x, ha);
            fma2(ago[0], w.y, ha);
            fma2(aif[1], w.x, hb);
            fma2(ago[1], w.y, hb);
        }

#pragma unroll
        for (int j = 0; j < 2; j++) {
            const int bi = bq + 4 * j;
            float2 gif = upk2(aif[j]);
            float2 ggo = upk2(ago[j]);
            float ig = sigm(gif.x);
            float fg = sigm(gif.y);
            float gg = tanhf(ggo.x);
            float og = sigm(ggo.y);
            float cn = fg * c_reg[j] + ig * gg;
            c_reg[j] = cn;
            float hn = og * tanhf(cn);
            u64 hdup = pk2(hn, hn);
            unsigned laddr = smem_u32(&h2[nxt][bi][kg]);
#pragma unroll
            for (int r = 0; r < 4; r++) dsmem_st64(laddr, r, hdup);
            g_lstm[(((size_t)(b0 + bi)) * TT + t) * 512 + d * 256 + kg] = hn;
        }

        asm volatile("barrier.cluster.arrive.aligned;" ::: "memory");
        asm volatile("barrier.cluster.wait.aligned;" ::: "memory");
    }
}

// ---------------- kernel 3: feats = lstm_out @ W_out^T + b_out ----------------
__global__ void __launch_bounds__(256) feats_kernel(
    const float* __restrict__ W_out, const float* __restrict__ b_out)
{
    const int m0  = blockIdx.x * 16;
    const int tid = threadIdx.x;

    __shared__ __align__(16) float Ws[76][68];
    __shared__ __align__(16) float Xs[16][64];

    float acc[5] = {0.f, 0.f, 0.f, 0.f, 0.f};
    const int r  = tid >> 4;
    const int jg = tid & 15;

    for (int k0 = 0; k0 < 512; k0 += 64) {
        for (int idx = tid; idx < 76 * 16; idx += 256) {
            int row = idx >> 4;
            int c4  = (idx & 15) * 4;
            float4 v = *(const float4*)(W_out + (size_t)row * 512 + k0 + c4);
            *(float4*)&Ws[row][c4] = v;
        }
        {
            int row = tid >> 4;
            int c4  = (tid & 15) * 4;
            *(float4*)&Xs[row][c4] =
                *(const float4*)(g_lstm + (size_t)(m0 + row) * 512 + k0 + c4);
        }
        __syncthreads();
#pragma unroll
        for (int kk = 0; kk < 64; kk += 4) {
            float4 x = *(const float4*)&Xs[r][kk];
#pragma unroll
            for (int u = 0; u < 5; u++) {
                int j = jg + u * 16;
                if (j < NT) {
                    float4 w = *(const float4*)&Ws[j][kk];
                    acc[u] = fmaf(x.x, w.x, acc[u]);
                    acc[u] = fmaf(x.y, w.y, acc[u]);
                    acc[u] = fmaf(x.z, w.z, acc[u]);
                    acc[u] = fmaf(x.w, w.w, acc[u]);
                }
            }
        }
        __syncthreads();
    }

#pragma unroll
    for (int u = 0; u < 5; u++) {
        int j = jg + u * 16;
        if (j < NT)
            g_feats[(size_t)(m0 + r) * NT + j] = acc[u] + b_out[j];
    }
}

// ---------------- kernel 4: Viterbi ----------------
__global__ void __launch_bounds__(128) viterbi_kernel(
    const float* __restrict__ trans, float* __restrict__ out)
{
    const int b   = blockIdx.x;
    const int tid = threadIdx.x;

    __shared__ float trans_s[NT * NT];
    __shared__ float fv0[NT], fv1[NT];
    __shared__ unsigned char bp[TT][NT];

    for (int i = tid; i < NT * NT; i += blockDim.x) trans_s[i] = trans[i];
    if (tid < NT) fv0[tid] = (tid == START_IDX) ? 0.0f : NEGV;
    __syncthreads();

    const float* __restrict__ feats_b = g_feats + (size_t)b * TT * NT;

    for (int t = 0; t < TT; t++) {
        float* fv  = (t & 1) ? fv1 : fv0;
        float* fvn = (t & 1) ? fv0 : fv1;
        if (tid < NT) {
            float best = -INFINITY;
            int arg = 0;
            const float* tr = trans_s + tid * NT;
#pragma unroll 4
            for (int p = 0; p < NT; p++) {
                float s = fv[p] + tr[p];
                if (s > best) { best = s; arg = p; }
            }
            fvn[tid] = best + feats_b[t * NT + tid];
            bp[t][tid] = (unsigned char)arg;
        }
        __syncthreads();
    }

    if (tid == 0) {
        float* fvF = fv0;
        float best = -INFINITY;
        int arg = 0;
        for (int j = 0; j < NT; j++) {
            float s = fvF[j] + trans_s[STOP_IDX * NT + j];
            if (s > best) { best = s; arg = j; }
        }
        out[b] = best;
        float* po = out + BB + (size_t)b * TT;
        int tag = arg;
        po[TT - 1] = (float)tag;
        for (int t = TT - 1; t >= 1; t--) {
            tag = bp[t][tag];
            po[t - 1] = (float)tag;
        }
    }
}

// ---------------- launch ----------------
extern "C" void kernel_launch(void* const* d_in, const int* in_sizes, int n_in,
                              void* d_out, int out_size) {
    const int*   ids    = (const int*)  d_in[0];
    const float* emb    = (const float*)d_in[1];
    const float* Wih_f  = (const float*)d_in[2];
    const float* Whh_f  = (const float*)d_in[3];
    const float* bih_f  = (const float*)d_in[4];
    const float* bhh_f  = (const float*)d_in[5];
    const float* Wih_b  = (const float*)d_in[6];
    const float* Whh_b  = (const float*)d_in[7];
    const float* bih_b  = (const float*)d_in[8];
    const float* bhh_b  = (const float*)d_in[9];
    const float* h0     = (const float*)d_in[10];
    const float* c0     = (const float*)d_in[11];
    const float* W_out  = (const float*)d_in[12];
    const float* b_out  = (const float*)d_in[13];
    const float* trans  = (const float*)d_in[14];
    float* out = (float*)d_out;

    (void)in_sizes; (void)n_in; (void)out_size;

    // shifts the fixed ncu capture slot from feats onto lstm_rec
    noop_kernel<<<1, 32>>>();

    {
        const size_t total = (size_t)2 * 1024 * 256;
        transpose_whh_kernel<<<(unsigned)((total + 255) / 256), 256>>>(Whh_f, Whh_b);
    }
    {
        const int smem_bytes = (128 * 128 + 128 * 64) * 4;   // 96 KB
        cudaFuncSetAttribute(pregemm_kernel,
                             cudaFuncAttributeMaxDynamicSharedMemorySize, smem_bytes);
        dim3 grid(G4H / PGN, (BB * TT) / PGM, 2);
        pregemm_kernel<<<grid, 256, smem_bytes>>>(ids, emb, Wih_f, Wih_b,
                                                  bih_f, bhh_f, bih_b, bhh_b);
    }
    lstm_rec_kernel<<<128, 256>>>(h0, c0);
    feats_kernel<<<(BB * TT) / 16, 256>>>(W_out, b_out);
    viterbi_kernel<<<BB, 128>>>(trans, out);
}

// round 6
// speedup vs baseline: 1.4838x; 1.2865x over previous
#include <cuda_runtime.h>
#include <cuda_bf16.h>
#include <math.h>

// ---------------- problem constants ----------------
#define BB   128
#define TT   256
#define EE   256
#define H2   256
#define G4H  1024
#define NT   76
#define START_IDX 74
#define STOP_IDX  75
#define NEGV (-10000.0f)

// ---------------- scratch ----------------
__device__ __align__(16) float g_xw[(size_t)2 * BB * TT * G4H];   // xw[d][m][n]
__device__ __align__(16) float g_lstm[(size_t)BB * TT * 512];     // [b][t][dir*256+k]
__device__ __align__(16) float g_feats[(size_t)BB * TT * NT];
// W3[d][ks][kk][kl][g] : kk-major slices per k-quarter
__device__ __align__(16) float g_W3[(size_t)2 * 4 * 256 * 64 * 4];

// ---------------- f32x2 helpers ----------------
typedef unsigned long long u64;

__device__ __forceinline__ u64 pk2(float lo, float hi) {
    u64 r; asm("mov.b64 %0, {%1, %2};" : "=l"(r) : "f"(lo), "f"(hi)); return r;
}
__device__ __forceinline__ void fma2(u64& d, u64 a, u64 b) {
    asm("fma.rn.f32x2 %0, %1, %2, %0;" : "+l"(d) : "l"(a), "l"(b));
}
__device__ __forceinline__ float2 upk2(u64 v) {
    float2 r; asm("mov.b64 {%0, %1}, %2;" : "=f"(r.x), "=f"(r.y) : "l"(v)); return r;
}
__device__ __forceinline__ float sigm(float x) {
    return 1.0f / (1.0f + expf(-x));
}
__device__ __forceinline__ unsigned smem_u32(const void* p) {
    unsigned a;
    asm("{ .reg .u64 t; cvta.to.shared.u64 t, %1; cvt.u32.u64 %0, t; }"
        : "=r"(a) : "l"(p));
    return a;
}
__device__ __forceinline__ void dsmem_st32(unsigned laddr, int rank, float v) {
    unsigned ra;
    asm volatile("mapa.shared::cluster.u32 %0, %1, %2;" : "=r"(ra) : "r"(laddr), "r"(rank));
    asm volatile("st.shared::cluster.b32 [%0], %1;" :: "r"(ra), "f"(v) : "memory");
}

// ---------------- kernel -1: no-op (keeps ncu capture slot on lstm) ----------------
__global__ void noop_kernel() {}

// ---------------- kernel 0: transpose Whh -> g_W3 ----------------
__global__ void transpose_whh_kernel(const float* __restrict__ Whh_f,
                                     const float* __restrict__ Whh_b) {
    size_t idx = (size_t)blockIdx.x * blockDim.x + threadIdx.x;
    const size_t total = (size_t)2 * 1024 * 256;
    if (idx >= total) return;
    int kk  = (int)(idx & 255);
    size_t r = idx >> 8;
    int row = (int)(r & 1023);
    int d   = (int)(r >> 10);
    int g  = row >> 8;
    int k  = row & 255;
    int ks = k >> 6;
    int kl = k & 63;
    const float* W = d ? Whh_b : Whh_f;
    g_W3[((((size_t)(d * 4 + ks)) * 256 + kk) * 64 + kl) * 4 + g] =
        W[(size_t)row * 256 + kk];
}

// ---------------- kernel 1: pre-GEMM v4 (unchanged; near FFMA2 floor) ----------------
#define PGM 128
#define PGN 64
__global__ void __launch_bounds__(256, 2) pregemm_kernel(
    const int*   __restrict__ ids,
    const float* __restrict__ emb,
    const float* __restrict__ Wih_f, const float* __restrict__ Wih_b,
    const float* __restrict__ bih_f, const float* __restrict__ bhh_f,
    const float* __restrict__ bih_b, const float* __restrict__ bhh_b)
{
    extern __shared__ __align__(16) float sm[];
    float* As = sm;                  // [kk 0..127][m 0..127]
    float* Bs = sm + 128 * 128;      // [kk 0..127][n 0..63]
    __shared__ int ids_s[PGM];

    const int d = blockIdx.z;
    const float* __restrict__ Wih = d ? Wih_b : Wih_f;
    const float* __restrict__ b1  = d ? bih_b : bih_f;
    const float* __restrict__ b2  = d ? bhh_b : bhh_f;

    const int m0 = blockIdx.y * PGM;
    const int n0 = blockIdx.x * PGN;
    const int tid = threadIdx.x;

    if (tid < PGM) ids_s[tid] = ids[m0 + tid];
    __syncthreads();

    const int tx = tid & 15;
    const int ty = tid >> 4;

    float bsum[4];
#pragma unroll
    for (int j = 0; j < 4; j++) {
        int n = n0 + tx * 4 + j;
        bsum[j] = b1[n] + b2[n];
    }

    u64 acc[4][4];
#pragma unroll
    for (int p = 0; p < 4; p++)
#pragma unroll
        for (int j = 0; j < 4; j++) acc[p][j] = 0ULL;

    const float* ap = As + ty * 8;
    const float* bp = Bs + tx * 4;

    const int ar  = tid >> 1;
    const int ac0 = (tid & 1) * 64;
    const float* asrc = emb + (size_t)ids_s[ar] * 256 + ac0;
    const int br  = tid >> 2;
    const int bc0 = (tid & 3) * 32;
    const float* bsrc = Wih + (size_t)(n0 + br) * 256 + bc0;

#pragma unroll
    for (int h = 0; h < 2; h++) {
        {
            const float* src = asrc + h * 128;
#pragma unroll
            for (int j = 0; j < 16; j++) {
                float4 v = *(const float4*)(src + j * 4);
                int c = ac0 + j * 4;
                As[(c + 0) * 128 + ar] = v.x;
                As[(c + 1) * 128 + ar] = v.y;
                As[(c + 2) * 128 + ar] = v.z;
                As[(c + 3) * 128 + ar] = v.w;
            }
        }
        {
            const float* src = bsrc + h * 128;
#pragma unroll
            for (int j = 0; j < 8; j++) {
                float4 v = *(const float4*)(src + j * 4);
                int c = bc0 + j * 4;
                Bs[(c + 0) * 64 + br] = v.x;
                Bs[(c + 1) * 64 + br] = v.y;
                Bs[(c + 2) * 64 + br] = v.z;
                Bs[(c + 3) * 64 + br] = v.w;
            }
        }
        __syncthreads();

#pragma unroll 4
        for (int kk = 0; kk < 128; kk++) {
            ulonglong2 a01 = *(const ulonglong2*)(ap + kk * 128);
            ulonglong2 a23 = *(const ulonglong2*)(ap + kk * 128 + 4);
            float4 b = *(const float4*)(bp + kk * 64);
            u64 bd[4];
            bd[0] = pk2(b.x, b.x); bd[1] = pk2(b.y, b.y);
            bd[2] = pk2(b.z, b.z); bd[3] = pk2(b.w, b.w);
#pragma unroll
            for (int j = 0; j < 4; j++) {
                fma2(acc[0][j], a01.x, bd[j]);
                fma2(acc[1][j], a01.y, bd[j]);
                fma2(acc[2][j], a23.x, bd[j]);
                fma2(acc[3][j], a23.y, bd[j]);
            }
        }
        __syncthreads();
    }

#pragma unroll
    for (int p = 0; p < 4; p++) {
        float2 v0 = upk2(acc[p][0]);
        float2 v1 = upk2(acc[p][1]);
        float2 v2 = upk2(acc[p][2]);
        float2 v3 = upk2(acc[p][3]);
        int mA = m0 + ty * 8 + 2 * p;
        float4 rA = {v0.x + bsum[0], v1.x + bsum[1], v2.x + bsum[2], v3.x + bsum[3]};
        float4 rB = {v0.y + bsum[0], v1.y + bsum[1], v2.y + bsum[2], v3.y + bsum[3]};
        *(float4*)(g_xw + ((size_t)d * (BB * TT) + mA) * G4H + n0 + tx * 4) = rA;
        *(float4*)(g_xw + ((size_t)d * (BB * TT) + mA + 1) * G4H + n0 + tx * 4) = rB;
    }
}

// ---------------- kernel 2: recurrent LSTM v3 ----------------
// cluster-4 k-split, G=8 batches. Weight slice kk 0..127 resident in 128KB smem
// (LDS, conflict-free); kk 128..255 streamed from L2. h stored plain float,
// read as float4/4kk (broadcast). xw(t+1) prefetched into registers.
// Accumulation order kk = 0..255 ascending (bitwise-identical to prior rounds).
#define HP 260
__global__ void __cluster_dims__(4, 1, 1) __launch_bounds__(256, 1)
lstm_rec_kernel(const float* __restrict__ h0, const float* __restrict__ c0)
{
    extern __shared__ __align__(16) float smw[];     // 128 kk x 64 kl x 4 g = 128KB
    __shared__ __align__(16) float hbuf[2][8][HP];

    const int cid  = blockIdx.x >> 2;
    const int rank = blockIdx.x & 3;
    const int d    = cid >> 4;
    const int grp  = cid & 15;
    const int b0   = grp * 8;
    const int tid  = threadIdx.x;
    const int kl   = tid >> 2;
    const int bq   = tid & 3;
    const int kg   = rank * 64 + kl;

    const float* __restrict__ wsrc =
        g_W3 + ((size_t)(d * 4 + rank)) * (256 * 64 * 4);

    // preload weight half (kk 0..127) into smem: 32768 floats, contiguous
    {
        const float4* src = (const float4*)wsrc;
        float4* dst = (float4*)smw;
#pragma unroll
        for (int j = 0; j < 32; j++)
            dst[tid + j * 256] = src[tid + j * 256];
    }

    // init h, c
#pragma unroll
    for (int bi = 0; bi < 8; bi++)
        hbuf[0][bi][tid] = h0[((size_t)d * BB + b0 + bi) * H2 + tid];
    float c_reg[2];
#pragma unroll
    for (int j = 0; j < 2; j++)
        c_reg[j] = c0[((size_t)d * BB + b0 + bq + 4 * j) * H2 + kg];
    __syncthreads();

    // xw registers for current step (prefetched each iteration)
    float xr[8];
    {
        const int t0 = d ? (TT - 1) : 0;
#pragma unroll
        for (int j = 0; j < 2; j++) {
            const float* xp =
                g_xw + (((size_t)d * BB + b0 + bq + 4 * j) * TT + t0) * G4H;
            xr[j * 4 + 0] = xp[kg];
            xr[j * 4 + 1] = xp[256 + kg];
            xr[j * 4 + 2] = xp[512 + kg];
            xr[j * 4 + 3] = xp[768 + kg];
        }
    }

    const float* __restrict__ wl2 = wsrc + 128 * 256;   // gmem half base (kk=128)

    for (int step = 0; step < TT; step++) {
        const int t   = d ? (TT - 1 - step) : step;
        const int cur = step & 1;
        const int nxt = cur ^ 1;

        u64 aif[2], ago[2];
        aif[0] = pk2(xr[0], xr[1]); ago[0] = pk2(xr[2], xr[3]);
        aif[1] = pk2(xr[4], xr[5]); ago[1] = pk2(xr[6], xr[7]);

        const float* hp0 = &hbuf[cur][bq][0];
        const float* hp1 = &hbuf[cur][bq + 4][0];
        const float* wsp = smw + kl * 4;

        // ---- kk 0..127 from smem ----
#pragma unroll 4
        for (int kk4 = 0; kk4 < 128; kk4 += 4) {
            float4 h4a = *(const float4*)(hp0 + kk4);
            float4 h4b = *(const float4*)(hp1 + kk4);
            float ha[4] = {h4a.x, h4a.y, h4a.z, h4a.w};
            float hb[4] = {h4b.x, h4b.y, h4b.z, h4b.w};
#pragma unroll
            for (int u = 0; u < 4; u++) {
                ulonglong2 w = *(const ulonglong2*)(wsp + (kk4 + u) * 256);
                u64 hda = pk2(ha[u], ha[u]);
                u64 hdb = pk2(hb[u], hb[u]);
                fma2(aif[0], w.x, hda);
                fma2(ago[0], w.y, hda);
                fma2(aif[1], w.x, hdb);
                fma2(ago[1], w.y, hdb);
            }
        }

        // ---- kk 128..255 from L2 ----
        const float* wgp = wl2 + kl * 4;
#pragma unroll 4
        for (int kk4 = 0; kk4 < 128; kk4 += 4) {
            float4 h4a = *(const float4*)(hp0 + 128 + kk4);
            float4 h4b = *(const float4*)(hp1 + 128 + kk4);
            float ha[4] = {h4a.x, h4a.y, h4a.z, h4a.w};
            float hb[4] = {h4b.x, h4b.y, h4b.z, h4b.w};
#pragma unroll
            for (int u = 0; u < 4; u++) {
                ulonglong2 w = *(const ulonglong2*)(wgp + (size_t)(kk4 + u) * 256);
                u64 hda = pk2(ha[u], ha[u]);
                u64 hdb = pk2(hb[u], hb[u]);
                fma2(aif[0], w.x, hda);
                fma2(ago[0], w.y, hda);
                fma2(aif[1], w.x, hdb);
                fma2(ago[1], w.y, hdb);
            }
        }

        // prefetch xw for next step (hidden behind activations/DSMEM/barrier)
        if (step + 1 < TT) {
            const int tn = d ? (TT - 2 - step) : (step + 1);
#pragma unroll
            for (int j = 0; j < 2; j++) {
                const float* xp =
                    g_xw + (((size_t)d * BB + b0 + bq + 4 * j) * TT + tn) * G4H;
                xr[j * 4 + 0] = xp[kg];
                xr[j * 4 + 1] = xp[256 + kg];
                xr[j * 4 + 2] = xp[512 + kg];
                xr[j * 4 + 3] = xp[768 + kg];
            }
        }

        // ---- gates, state update, h broadcast ----
#pragma unroll
        for (int j = 0; j < 2; j++) {
            const int bi = bq + 4 * j;
            float2 gif = upk2(aif[j]);
            float2 ggo = upk2(ago[j]);
            float ig = sigm(gif.x);
            float fg = sigm(gif.y);
            float gg = tanhf(ggo.x);
            float og = sigm(ggo.y);
            float cn = fg * c_reg[j] + ig * gg;
            c_reg[j] = cn;
            float hn = og * tanhf(cn);
            unsigned laddr = smem_u32(&hbuf[nxt][bi][kg]);
#pragma unroll
            for (int r = 0; r < 4; r++) dsmem_st32(laddr, r, hn);
            g_lstm[(((size_t)(b0 + bi)) * TT + t) * 512 + d * 256 + kg] = hn;
        }

        asm volatile("barrier.cluster.arrive.aligned;" ::: "memory");
        asm volatile("barrier.cluster.wait.aligned;" ::: "memory");
    }
}

// ---------------- kernel 3: feats = lstm_out @ W_out^T + b_out ----------------
__global__ void __launch_bounds__(256) feats_kernel(
    const float* __restrict__ W_out, const float* __restrict__ b_out)
{
    const int m0  = blockIdx.x * 16;
    const int tid = threadIdx.x;

    __shared__ __align__(16) float Ws[76][68];
    __shared__ __align__(16) float Xs[16][64];

    float acc[5] = {0.f, 0.f, 0.f, 0.f, 0.f};
    const int r  = tid >> 4;
    const int jg = tid & 15;

    for (int k0 = 0; k0 < 512; k0 += 64) {
        for (int idx = tid; idx < 76 * 16; idx += 256) {
            int row = idx >> 4;
            int c4  = (idx & 15) * 4;
            float4 v = *(const float4*)(W_out + (size_t)row * 512 + k0 + c4);
            *(float4*)&Ws[row][c4] = v;
        }
        {
            int row = tid >> 4;
            int c4  = (tid & 15) * 4;
            *(float4*)&Xs[row][c4] =
                *(const float4*)(g_lstm + (size_t)(m0 + row) * 512 + k0 + c4);
        }
        __syncthreads();
#pragma unroll
        for (int kk = 0; kk < 64; kk += 4) {
            float4 x = *(const float4*)&Xs[r][kk];
#pragma unroll
            for (int u = 0; u < 5; u++) {
                int j = jg + u * 16;
                if (j < NT) {
                    float4 w = *(const float4*)&Ws[j][kk];
                    acc[u] = fmaf(x.x, w.x, acc[u]);
                    acc[u] = fmaf(x.y, w.y, acc[u]);
                    acc[u] = fmaf(x.z, w.z, acc[u]);
                    acc[u] = fmaf(x.w, w.w, acc[u]);
                }
            }
        }
        __syncthreads();
    }

#pragma unroll
    for (int u = 0; u < 5; u++) {
        int j = jg + u * 16;
        if (j < NT)
            g_feats[(size_t)(m0 + r) * NT + j] = acc[u] + b_out[j];
    }
}

// ---------------- kernel 4: Viterbi ----------------
__global__ void __launch_bounds__(128) viterbi_kernel(
    const float* __restrict__ trans, float* __restrict__ out)
{
    const int b   = blockIdx.x;
    const int tid = threadIdx.x;

    __shared__ float trans_s[NT * NT];
    __shared__ float fv0[NT], fv1[NT];
    __shared__ unsigned char bp[TT][NT];

    for (int i = tid; i < NT * NT; i += blockDim.x) trans_s[i] = trans[i];
    if (tid < NT) fv0[tid] = (tid == START_IDX) ? 0.0f : NEGV;
    __syncthreads();

    const float* __restrict__ feats_b = g_feats + (size_t)b * TT * NT;

    for (int t = 0; t < TT; t++) {
        float* fv  = (t & 1) ? fv1 : fv0;
        float* fvn = (t & 1) ? fv0 : fv1;
        if (tid < NT) {
            float best = -INFINITY;
            int arg = 0;
            const float* tr = trans_s + tid * NT;
#pragma unroll 4
            for (int p = 0; p < NT; p++) {
                float s = fv[p] + tr[p];
                if (s > best) { best = s; arg = p; }
            }
            fvn[tid] = best + feats_b[t * NT + tid];
            bp[t][tid] = (unsigned char)arg;
        }
        __syncthreads();
    }

    if (tid == 0) {
        float* fvF = fv0;
        float best = -INFINITY;
        int arg = 0;
        for (int j = 0; j < NT; j++) {
            float s = fvF[j] + trans_s[STOP_IDX * NT + j];
            if (s > best) { best = s; arg = j; }
        }
        out[b] = best;
        float* po = out + BB + (size_t)b * TT;
        int tag = arg;
        po[TT - 1] = (float)tag;
        for (int t = TT - 1; t >= 1; t--) {
            tag = bp[t][tag];
            po[t - 1] = (float)tag;
        }
    }
}

// ---------------- launch ----------------
extern "C" void kernel_launch(void* const* d_in, const int* in_sizes, int n_in,
                              void* d_out, int out_size) {
    const int*   ids    = (const int*)  d_in[0];
    const float* emb    = (const float*)d_in[1];
    const float* Wih_f  = (const float*)d_in[2];
    const float* Whh_f  = (const float*)d_in[3];
    const float* bih_f  = (const float*)d_in[4];
    const float* bhh_f  = (const float*)d_in[5];
    const float* Wih_b  = (const float*)d_in[6];
    const float* Whh_b  = (const float*)d_in[7];
    const float* bih_b  = (const float*)d_in[8];
    const float* bhh_b  = (const float*)d_in[9];
    const float* h0     = (const float*)d_in[10];
    const float* c0     = (const float*)d_in[11];
    const float* W_out  = (const float*)d_in[12];
    const float* b_out  = (const float*)d_in[13];
    const float* trans  = (const float*)d_in[14];
    float* out = (float*)d_out;

    (void)in_sizes; (void)n_in; (void)out_size;

    // keeps the fixed ncu capture slot on lstm_rec
    noop_kernel<<<1, 32>>>();

    {
        const size_t total = (size_t)2 * 1024 * 256;
        transpose_whh_kernel<<<(unsigned)((total + 255) / 256), 256>>>(Whh_f, Whh_b);
    }
    {
        const int smem_bytes = (128 * 128 + 128 * 64) * 4;   // 96 KB
        cudaFuncSetAttribute(pregemm_kernel,
                             cudaFuncAttributeMaxDynamicSharedMemorySize, smem_bytes);
        dim3 grid(G4H / PGN, (BB * TT) / PGM, 2);
        pregemm_kernel<<<grid, 256, smem_bytes>>>(ids, emb, Wih_f, Wih_b,
                                                  bih_f, bhh_f, bih_b, bhh_b);
    }
    {
        const int lstm_smem = 128 * 256 * 4;                 // 128 KB weights
        cudaFuncSetAttribute(lstm_rec_kernel,
                             cudaFuncAttributeMaxDynamicSharedMemorySize, lstm_smem);
        lstm_rec_kernel<<<128, 256, lstm_smem>>>(h0, c0);
    }
    feats_kernel<<<(BB * TT) / 16, 256>>>(W_out, b_out);
    viterbi_kernel<<<BB, 128>>>(trans, out);
}